// round 3
// baseline (speedup 1.0000x reference)
#include <cuda_runtime.h>
#include <math.h>

// Problem constants
#define NN_ 4096
#define DD_ 1024
#define HH_ 8
#define DH_ 128
#define FF_ 2048   // 2*D

static const size_t SZ_ND = (size_t)NN_ * DD_;      // 4,194,304
static const size_t SZ_NN = (size_t)NN_ * NN_;      // 16,777,216
static const size_t SZ_NF = (size_t)NN_ * FF_;      // 8,388,608

// Scratch layout: Q,K,V,AO,P,H,F (7*SZ_ND) | S (8*SZ_NN) | T (SZ_NF)
__device__ float g_scratch[7 * 4194304ull + 8 * 16777216ull + 8388608ull];

// ---------------------------------------------------------------------------
// Tiled SGEMM: C = A @ B (or A @ B^T when TB), 128x128 tile, BK=8, 8x8 microtile
// Batched over blockIdx.z with element strides sA/sB/sC.
// EPI: 0 = none, 1 = +bias[col], 2 = gelu(+bias), 3 = +bias + addm,
//      4 = acc*scale + beta[z]*adj[row,col]
// All dims assumed multiples of the tile (true for this problem).
// ---------------------------------------------------------------------------
#define BM 128
#define BN 128
#define BK 8
#define TM 8
#define TN 8

template <bool TB, int EPI>
__global__ void __launch_bounds__(256, 2) gemm_k(
    const float* __restrict__ A, const float* __restrict__ B, float* __restrict__ C,
    int M, int Nn, int K, int lda, int ldb, int ldc,
    long long sA, long long sB, long long sC,
    const float* __restrict__ bias,
    const float* __restrict__ addm, int ldadd,
    const float* __restrict__ adj, int ldadj, float scale,
    const float* __restrict__ beta_ptr)
{
    __shared__ float As[BK][BM];
    __shared__ float Bs[BK][BN];

    const int z = blockIdx.z;
    A += (size_t)z * sA;
    B += (size_t)z * sB;
    C += (size_t)z * sC;

    const int tid  = threadIdx.x;
    const int row0 = blockIdx.y * BM;
    const int col0 = blockIdx.x * BN;
    const int tx = tid & 15;
    const int ty = tid >> 4;

    // A-load (and TB B-load) indices: one float4 along K per thread
    const int aRow = tid >> 1;        // 0..127
    const int aCol = (tid & 1) * 4;   // 0 or 4
    // NN B-load indices
    const int bRow = tid >> 5;        // 0..7
    const int bCol = (tid & 31) * 4;  // 0..124

    float acc[TM][TN];
#pragma unroll
    for (int i = 0; i < TM; i++)
#pragma unroll
        for (int j = 0; j < TN; j++) acc[i][j] = 0.f;

    for (int k0 = 0; k0 < K; k0 += BK) {
        float4 av = *(const float4*)(A + (size_t)(row0 + aRow) * lda + k0 + aCol);
        As[aCol + 0][aRow] = av.x;
        As[aCol + 1][aRow] = av.y;
        As[aCol + 2][aRow] = av.z;
        As[aCol + 3][aRow] = av.w;
        if (TB) {
            float4 bv = *(const float4*)(B + (size_t)(col0 + aRow) * ldb + k0 + aCol);
            Bs[aCol + 0][aRow] = bv.x;
            Bs[aCol + 1][aRow] = bv.y;
            Bs[aCol + 2][aRow] = bv.z;
            Bs[aCol + 3][aRow] = bv.w;
        } else {
            float4 bv = *(const float4*)(B + (size_t)(k0 + bRow) * ldb + col0 + bCol);
            *(float4*)&Bs[bRow][bCol] = bv;
        }
        __syncthreads();

#pragma unroll
        for (int k = 0; k < BK; ++k) {
            float a[TM], b[TN];
            float4 a0 = *(const float4*)&As[k][ty * TM];
            float4 a1 = *(const float4*)&As[k][ty * TM + 4];
            a[0]=a0.x; a[1]=a0.y; a[2]=a0.z; a[3]=a0.w;
            a[4]=a1.x; a[5]=a1.y; a[6]=a1.z; a[7]=a1.w;
            float4 b0 = *(const float4*)&Bs[k][tx * TN];
            float4 b1 = *(const float4*)&Bs[k][tx * TN + 4];
            b[0]=b0.x; b[1]=b0.y; b[2]=b0.z; b[3]=b0.w;
            b[4]=b1.x; b[5]=b1.y; b[6]=b1.z; b[7]=b1.w;
#pragma unroll
            for (int i = 0; i < TM; i++)
#pragma unroll
                for (int j = 0; j < TN; j++)
                    acc[i][j] = fmaf(a[i], b[j], acc[i][j]);
        }
        __syncthreads();
    }

    float beta = 0.f;
    if (EPI == 4) beta = beta_ptr[z];

#pragma unroll
    for (int i = 0; i < TM; i++) {
        const int r = row0 + ty * TM + i;
#pragma unroll
        for (int j = 0; j < TN; j++) {
            const int c = col0 + tx * TN + j;
            float v = acc[i][j];
            if (EPI == 1) {
                v += bias[c];
            } else if (EPI == 2) {
                v += bias[c];
                v = 0.5f * v * (1.f + erff(v * 0.70710678118654752f));
            } else if (EPI == 3) {
                v += bias[c] + addm[(size_t)r * ldadd + c];
            } else if (EPI == 4) {
                v = v * scale + beta * adj[(size_t)r * ldadj + c];
            }
            C[(size_t)r * ldc + c] = v;
        }
    }
}

// ---------------------------------------------------------------------------
// Row softmax over 4096 elements; grid = (4096 rows, 8 heads)
// ---------------------------------------------------------------------------
__global__ void __launch_bounds__(256) softmax4096(float* __restrict__ S)
{
    __shared__ float red[256];
    const int tid = threadIdx.x;
    float4* p = (float4*)(S + ((size_t)blockIdx.y * NN_ + blockIdx.x) * NN_);

    float4 d0 = p[tid], d1 = p[tid + 256], d2 = p[tid + 512], d3 = p[tid + 768];

    float mx = fmaxf(fmaxf(fmaxf(d0.x, d0.y), fmaxf(d0.z, d0.w)),
                     fmaxf(fmaxf(d1.x, d1.y), fmaxf(d1.z, d1.w)));
    mx = fmaxf(mx, fmaxf(fmaxf(d2.x, d2.y), fmaxf(d2.z, d2.w)));
    mx = fmaxf(mx, fmaxf(fmaxf(d3.x, d3.y), fmaxf(d3.z, d3.w)));
    red[tid] = mx;
    __syncthreads();
    for (int s = 128; s > 0; s >>= 1) {
        if (tid < s) red[tid] = fmaxf(red[tid], red[tid + s]);
        __syncthreads();
    }
    mx = red[0];
    __syncthreads();

#define EXP4(v) v.x = __expf(v.x - mx); v.y = __expf(v.y - mx); \
                v.z = __expf(v.z - mx); v.w = __expf(v.w - mx);
    EXP4(d0) EXP4(d1) EXP4(d2) EXP4(d3)
#undef EXP4
    float sum = (d0.x + d0.y + d0.z + d0.w) + (d1.x + d1.y + d1.z + d1.w)
              + (d2.x + d2.y + d2.z + d2.w) + (d3.x + d3.y + d3.z + d3.w);
    red[tid] = sum;
    __syncthreads();
    for (int s = 128; s > 0; s >>= 1) {
        if (tid < s) red[tid] += red[tid + s];
        __syncthreads();
    }
    const float inv = 1.0f / red[0];

#define SCL4(v) v.x *= inv; v.y *= inv; v.z *= inv; v.w *= inv;
    SCL4(d0) SCL4(d1) SCL4(d2) SCL4(d3)
#undef SCL4
    p[tid] = d0; p[tid + 256] = d1; p[tid + 512] = d2; p[tid + 768] = d3;
}

// ---------------------------------------------------------------------------
// Row LayerNorm over D=1024: out = LN(X + R) * g + b   (R optional)
// ---------------------------------------------------------------------------
__global__ void __launch_bounds__(256) ln_row(
    const float* __restrict__ X, const float* __restrict__ R,
    const float* __restrict__ g, const float* __restrict__ b,
    float* __restrict__ out)
{
    __shared__ float red[256];
    const int tid = threadIdx.x;
    const size_t row = blockIdx.x;

    float4 v = ((const float4*)(X + row * DD_))[tid];
    if (R) {
        float4 r = ((const float4*)(R + row * DD_))[tid];
        v.x += r.x; v.y += r.y; v.z += r.z; v.w += r.w;
    }
    red[tid] = v.x + v.y + v.z + v.w;
    __syncthreads();
    for (int s = 128; s > 0; s >>= 1) {
        if (tid < s) red[tid] += red[tid + s];
        __syncthreads();
    }
    const float mu = red[0] * (1.0f / DD_);
    __syncthreads();

    float dx = v.x - mu, dy = v.y - mu, dz = v.z - mu, dw = v.w - mu;
    red[tid] = dx * dx + dy * dy + dz * dz + dw * dw;
    __syncthreads();
    for (int s = 128; s > 0; s >>= 1) {
        if (tid < s) red[tid] += red[tid + s];
        __syncthreads();
    }
    const float rs = rsqrtf(red[0] * (1.0f / DD_) + 1e-5f);

    float4 gg = ((const float4*)g)[tid];
    float4 bb = ((const float4*)b)[tid];
    float4 o;
    o.x = dx * rs * gg.x + bb.x;
    o.y = dy * rs * gg.y + bb.y;
    o.z = dz * rs * gg.z + bb.z;
    o.w = dw * rs * gg.w + bb.w;
    ((float4*)(out + row * DD_))[tid] = o;
}

// ---------------------------------------------------------------------------
extern "C" void kernel_launch(void* const* d_in, const int* in_sizes, int n_in,
                              void* d_out, int out_size)
{
    const float* x        = (const float*)d_in[0];
    const float* adj      = (const float*)d_in[1];
    const float* Wq       = (const float*)d_in[2];
    const float* Wk       = (const float*)d_in[3];
    const float* Wv       = (const float*)d_in[4];
    const float* Wo_w     = (const float*)d_in[5];
    const float* Wo_b     = (const float*)d_in[6];
    const float* adj_bias = (const float*)d_in[7];
    const float* ln1_g    = (const float*)d_in[8];
    const float* ln1_b    = (const float*)d_in[9];
    const float* ffn_ln_g = (const float*)d_in[10];
    const float* ffn_ln_b = (const float*)d_in[11];
    const float* ffn_w1   = (const float*)d_in[12];
    const float* ffn_b1   = (const float*)d_in[13];
    const float* ffn_w2   = (const float*)d_in[14];
    const float* ffn_b2   = (const float*)d_in[15];
    float* out = (float*)d_out;

    float* scr = nullptr;
    cudaGetSymbolAddress((void**)&scr, g_scratch);

    float* Q  = scr + 0 * SZ_ND;
    float* Kb = scr + 1 * SZ_ND;
    float* V  = scr + 2 * SZ_ND;
    float* AO = scr + 3 * SZ_ND;
    float* P  = scr + 4 * SZ_ND;
    float* Hb = scr + 5 * SZ_ND;
    float* Fb = scr + 6 * SZ_ND;
    float* S  = scr + 7 * SZ_ND;
    float* T  = S + 8 * SZ_NN;

    const int TH = 256;
    const float scale = 0.08838834764831845f;  // 128^-0.5

    // --- Q/K/V projections: (4096x1024) @ (1024x1024)
    dim3 gqkv(DD_ / BN, NN_ / BM);
    gemm_k<false, 0><<<gqkv, TH>>>(x, Wq, Q, NN_, DD_, DD_, DD_, DD_, DD_,
                                   0, 0, 0, nullptr, nullptr, 0, nullptr, 0, 0.f, nullptr);
    gemm_k<false, 0><<<gqkv, TH>>>(x, Wk, Kb, NN_, DD_, DD_, DD_, DD_, DD_,
                                   0, 0, 0, nullptr, nullptr, 0, nullptr, 0, 0.f, nullptr);
    gemm_k<false, 0><<<gqkv, TH>>>(x, Wv, V, NN_, DD_, DD_, DD_, DD_, DD_,
                                   0, 0, 0, nullptr, nullptr, 0, nullptr, 0, 0.f, nullptr);

    // --- Scores: S[h] = scale * Q_h K_h^T + beta_h * adj   (batched over heads)
    dim3 gsc(NN_ / BN, NN_ / BM, HH_);
    gemm_k<true, 4><<<gsc, TH>>>(Q, Kb, S, NN_, NN_, DH_, DD_, DD_, NN_,
                                 DH_, DH_, (long long)SZ_NN,
                                 nullptr, nullptr, 0, adj, NN_, scale, adj_bias);

    // --- Softmax over rows of each head's S
    softmax4096<<<dim3(NN_, HH_), TH>>>(S);

    // --- O_h = S[h] @ V_h   (batched over heads)
    dim3 gav(DH_ / BN, NN_ / BM, HH_);
    gemm_k<false, 0><<<gav, TH>>>(S, V, AO, NN_, DH_, NN_, NN_, DD_, DD_,
                                  (long long)SZ_NN, DH_, DH_,
                                  nullptr, nullptr, 0, nullptr, 0, 0.f, nullptr);

    // --- Output projection with bias
    gemm_k<false, 1><<<gqkv, TH>>>(AO, Wo_w, P, NN_, DD_, DD_, DD_, DD_, DD_,
                                   0, 0, 0, Wo_b, nullptr, 0, nullptr, 0, 0.f, nullptr);

    // --- h = LN(x + P);  f = LN(h)
    ln_row<<<NN_, TH>>>(x, P, ln1_g, ln1_b, Hb);
    ln_row<<<NN_, TH>>>(Hb, nullptr, ffn_ln_g, ffn_ln_b, Fb);

    // --- FFN1 with fused exact GELU: T = gelu(F @ W1 + b1)
    dim3 gf1(FF_ / BN, NN_ / BM);
    gemm_k<false, 2><<<gf1, TH>>>(Fb, ffn_w1, T, NN_, FF_, DD_, DD_, FF_, FF_,
                                  0, 0, 0, ffn_b1, nullptr, 0, nullptr, 0, 0.f, nullptr);

    // --- FFN2 + bias + residual h: out = T @ W2 + b2 + h
    dim3 gf2(DD_ / BN, NN_ / BM);
    gemm_k<false, 3><<<gf2, TH>>>(T, ffn_w2, out, NN_, DD_, FF_, FF_, DD_, DD_,
                                  0, 0, 0, ffn_b2, Hb, DD_, nullptr, 0, 0.f, nullptr);
}

// round 6
// speedup vs baseline: 2.0321x; 2.0321x over previous
#include <cuda_runtime.h>
#include <math.h>

// Problem constants
#define NN_ 4096
#define DD_ 1024
#define HH_ 8
#define DH_ 128
#define FF_ 2048   // 2*D

static const size_t SZ_ND = (size_t)NN_ * DD_;      // 4,194,304
static const size_t SZ_NN = (size_t)NN_ * NN_;      // 16,777,216
static const size_t SZ_NF = (size_t)NN_ * FF_;      // 8,388,608

// Scratch layout: Q,K,V,AO,P,H,F (7*SZ_ND) | S (8*SZ_NN) | T (SZ_NF)
__device__ float g_scratch[7 * 4194304ull + 8 * 16777216ull + 8388608ull];

// ---------------------------------------------------------------------------
// TF32 helpers
// ---------------------------------------------------------------------------
__device__ __forceinline__ unsigned f2tf(float f) {
    unsigned u;
    asm("cvt.rna.tf32.f32 %0, %1;" : "=r"(u) : "f"(f));
    return u;
}

__device__ __forceinline__ void mma_tf32(float* d, const unsigned* a, const unsigned* b) {
    asm volatile(
        "mma.sync.aligned.m16n8k8.row.col.f32.tf32.tf32.f32 "
        "{%0,%1,%2,%3}, {%4,%5,%6,%7}, {%8,%9}, {%0,%1,%2,%3};"
        : "+f"(d[0]), "+f"(d[1]), "+f"(d[2]), "+f"(d[3])
        : "r"(a[0]), "r"(a[1]), "r"(a[2]), "r"(a[3]), "r"(b[0]), "r"(b[1]));
}

// ---------------------------------------------------------------------------
// TF32 tensor-core GEMM: C = A @ B (or A @ B^T when TB)
// Block tile 128x128, BK=16, 8 warps, warp tile 32x64 (2x8 m16n8k8 atoms).
// Double-buffered smem, register-staged global loads, tf32 conversion at STS.
// Batched over blockIdx.z with element strides sA/sB/sC.
// EPI: 0 = none, 1 = +bias[col], 2 = gelu(+bias), 3 = +bias + addm,
//      4 = acc*scale + beta[z]*adj[row,col]
// All dims are multiples of the tile / BK for this problem.
// ---------------------------------------------------------------------------
#define BM 128
#define BN 128
#define BK 16

template <bool TB, int EPI>
__global__ void __launch_bounds__(256, 2) gemm_tc(
    const float* __restrict__ A, const float* __restrict__ B, float* __restrict__ C,
    int K, int lda, int ldb, int ldc,
    long long sA, long long sB, long long sC,
    const float* __restrict__ bias,
    const float* __restrict__ addm, int ldadd,
    const float* __restrict__ adj, int ldadj, float scale,
    const float* __restrict__ beta_ptr)
{
    __shared__ __align__(16) unsigned As[2][BK][BM + 8];
    __shared__ __align__(16) unsigned Bs[2][BK][BN + 8];

    const int z = blockIdx.z;
    A += (size_t)z * sA;
    B += (size_t)z * sB;
    C += (size_t)z * sC;

    const int tid  = threadIdx.x;
    const int lane = tid & 31;
    const int wid  = tid >> 5;
    const int gid  = lane >> 2;   // 0..7
    const int tq   = lane & 3;    // 0..3
    const int wm0  = (wid & 3) * 32;   // warp m offset within tile
    const int wn0  = (wid >> 2) * 64;  // warp n offset within tile
    const int row0 = blockIdx.y * BM;
    const int col0 = blockIdx.x * BN;

    // A (and TB-B) load mapping: float4 along K, transpose into smem.
    const int ar  = tid & 127;          // row within tile
    const int ac0 = (tid >> 7) * 4;     // k offset: 0 or 4 (second load +8)
    // non-TB B load mapping: float4 along N.
    const int bk  = tid >> 5;           // k row 0..7 (second load +8)
    const int bn4 = (tid & 31) * 4;     // n offset

    const float* Aptr = A + (size_t)(row0 + ar) * lda + ac0;
    const float* Bptr;
    if (TB) Bptr = B + (size_t)(col0 + ar) * ldb + ac0;
    else    Bptr = B + (size_t)bk * ldb + col0 + bn4;

    float acc[2][8][4];
#pragma unroll
    for (int mt = 0; mt < 2; mt++)
#pragma unroll
        for (int nt = 0; nt < 8; nt++)
#pragma unroll
            for (int c = 0; c < 4; c++) acc[mt][nt][c] = 0.f;

    float4 aR0, aR1, bR0, bR1;

    // prologue loads (k0 = 0)
    aR0 = *(const float4*)(Aptr);
    aR1 = *(const float4*)(Aptr + 8);
    if (TB) {
        bR0 = *(const float4*)(Bptr);
        bR1 = *(const float4*)(Bptr + 8);
    } else {
        bR0 = *(const float4*)(Bptr);
        bR1 = *(const float4*)(Bptr + (size_t)8 * ldb);
    }

    auto sts = [&](int buf) {
        As[buf][ac0 + 0][ar] = f2tf(aR0.x);
        As[buf][ac0 + 1][ar] = f2tf(aR0.y);
        As[buf][ac0 + 2][ar] = f2tf(aR0.z);
        As[buf][ac0 + 3][ar] = f2tf(aR0.w);
        As[buf][ac0 + 8][ar] = f2tf(aR1.x);
        As[buf][ac0 + 9][ar] = f2tf(aR1.y);
        As[buf][ac0 + 10][ar] = f2tf(aR1.z);
        As[buf][ac0 + 11][ar] = f2tf(aR1.w);
        if (TB) {
            Bs[buf][ac0 + 0][ar] = f2tf(bR0.x);
            Bs[buf][ac0 + 1][ar] = f2tf(bR0.y);
            Bs[buf][ac0 + 2][ar] = f2tf(bR0.z);
            Bs[buf][ac0 + 3][ar] = f2tf(bR0.w);
            Bs[buf][ac0 + 8][ar] = f2tf(bR1.x);
            Bs[buf][ac0 + 9][ar] = f2tf(bR1.y);
            Bs[buf][ac0 + 10][ar] = f2tf(bR1.z);
            Bs[buf][ac0 + 11][ar] = f2tf(bR1.w);
        } else {
            uint4 u0 = make_uint4(f2tf(bR0.x), f2tf(bR0.y), f2tf(bR0.z), f2tf(bR0.w));
            uint4 u1 = make_uint4(f2tf(bR1.x), f2tf(bR1.y), f2tf(bR1.z), f2tf(bR1.w));
            *(uint4*)&Bs[buf][bk][bn4] = u0;
            *(uint4*)&Bs[buf][bk + 8][bn4] = u1;
        }
    };

    auto compute = [&](int buf) {
#pragma unroll
        for (int ks = 0; ks < 2; ks++) {
            const int kb = ks * 8;
            unsigned af[2][4], bf[8][2];
#pragma unroll
            for (int mt = 0; mt < 2; mt++) {
                const int m = wm0 + mt * 16 + gid;
                af[mt][0] = As[buf][kb + tq][m];
                af[mt][1] = As[buf][kb + tq][m + 8];
                af[mt][2] = As[buf][kb + tq + 4][m];
                af[mt][3] = As[buf][kb + tq + 4][m + 8];
            }
#pragma unroll
            for (int nt = 0; nt < 8; nt++) {
                const int n = wn0 + nt * 8 + gid;
                bf[nt][0] = Bs[buf][kb + tq][n];
                bf[nt][1] = Bs[buf][kb + tq + 4][n];
            }
#pragma unroll
            for (int mt = 0; mt < 2; mt++)
#pragma unroll
                for (int nt = 0; nt < 8; nt++)
                    mma_tf32(acc[mt][nt], af[mt], bf[nt]);
        }
    };

    int buf = 0;
    sts(0);
    __syncthreads();

    for (int k0 = BK; k0 < K; k0 += BK) {
        // issue next tile's global loads early
        aR0 = *(const float4*)(Aptr + k0);
        aR1 = *(const float4*)(Aptr + k0 + 8);
        if (TB) {
            bR0 = *(const float4*)(Bptr + k0);
            bR1 = *(const float4*)(Bptr + k0 + 8);
        } else {
            bR0 = *(const float4*)(Bptr + (size_t)k0 * ldb);
            bR1 = *(const float4*)(Bptr + (size_t)(k0 + 8) * ldb);
        }
        compute(buf);
        sts(buf ^ 1);
        __syncthreads();
        buf ^= 1;
    }
    compute(buf);

    // -------- epilogue --------
    float beta = 0.f;
    if (EPI == 4) beta = beta_ptr[z];

#pragma unroll
    for (int mt = 0; mt < 2; mt++) {
        const int r = row0 + wm0 + mt * 16 + gid;
#pragma unroll
        for (int nt = 0; nt < 8; nt++) {
            const int c = col0 + wn0 + nt * 8 + 2 * tq;
            float v0 = acc[mt][nt][0];
            float v1 = acc[mt][nt][1];
            float v2 = acc[mt][nt][2];
            float v3 = acc[mt][nt][3];
            if (EPI == 1) {
                v0 += bias[c]; v1 += bias[c + 1];
                v2 += bias[c]; v3 += bias[c + 1];
            } else if (EPI == 2) {
                v0 += bias[c]; v1 += bias[c + 1];
                v2 += bias[c]; v3 += bias[c + 1];
                v0 = 0.5f * v0 * (1.f + erff(v0 * 0.70710678118654752f));
                v1 = 0.5f * v1 * (1.f + erff(v1 * 0.70710678118654752f));
                v2 = 0.5f * v2 * (1.f + erff(v2 * 0.70710678118654752f));
                v3 = 0.5f * v3 * (1.f + erff(v3 * 0.70710678118654752f));
            } else if (EPI == 3) {
                float2 m0 = *(const float2*)&addm[(size_t)r * ldadd + c];
                float2 m1 = *(const float2*)&addm[(size_t)(r + 8) * ldadd + c];
                v0 += bias[c] + m0.x;     v1 += bias[c + 1] + m0.y;
                v2 += bias[c] + m1.x;     v3 += bias[c + 1] + m1.y;
            } else if (EPI == 4) {
                float2 j0 = *(const float2*)&adj[(size_t)r * ldadj + c];
                float2 j1 = *(const float2*)&adj[(size_t)(r + 8) * ldadj + c];
                v0 = v0 * scale + beta * j0.x;  v1 = v1 * scale + beta * j0.y;
                v2 = v2 * scale + beta * j1.x;  v3 = v3 * scale + beta * j1.y;
            }
            float2 o0 = make_float2(v0, v1);
            float2 o1 = make_float2(v2, v3);
            *(float2*)&C[(size_t)r * ldc + c] = o0;
            *(float2*)&C[(size_t)(r + 8) * ldc + c] = o1;
        }
    }
}

// ---------------------------------------------------------------------------
// Row softmax over 4096 elements; grid = (4096 rows, 8 heads)
// ---------------------------------------------------------------------------
__global__ void __launch_bounds__(256) softmax4096(float* __restrict__ S)
{
    __shared__ float red[256];
    const int tid = threadIdx.x;
    float4* p = (float4*)(S + ((size_t)blockIdx.y * NN_ + blockIdx.x) * NN_);

    float4 d0 = p[tid], d1 = p[tid + 256], d2 = p[tid + 512], d3 = p[tid + 768];

    float mx = fmaxf(fmaxf(fmaxf(d0.x, d0.y), fmaxf(d0.z, d0.w)),
                     fmaxf(fmaxf(d1.x, d1.y), fmaxf(d1.z, d1.w)));
    mx = fmaxf(mx, fmaxf(fmaxf(d2.x, d2.y), fmaxf(d2.z, d2.w)));
    mx = fmaxf(mx, fmaxf(fmaxf(d3.x, d3.y), fmaxf(d3.z, d3.w)));
    red[tid] = mx;
    __syncthreads();
    for (int s = 128; s > 0; s >>= 1) {
        if (tid < s) red[tid] = fmaxf(red[tid], red[tid + s]);
        __syncthreads();
    }
    mx = red[0];
    __syncthreads();

#define EXP4(v) v.x = __expf(v.x - mx); v.y = __expf(v.y - mx); \
                v.z = __expf(v.z - mx); v.w = __expf(v.w - mx);
    EXP4(d0) EXP4(d1) EXP4(d2) EXP4(d3)
#undef EXP4
    float sum = (d0.x + d0.y + d0.z + d0.w) + (d1.x + d1.y + d1.z + d1.w)
              + (d2.x + d2.y + d2.z + d2.w) + (d3.x + d3.y + d3.z + d3.w);
    red[tid] = sum;
    __syncthreads();
    for (int s = 128; s > 0; s >>= 1) {
        if (tid < s) red[tid] += red[tid + s];
        __syncthreads();
    }
    const float inv = 1.0f / red[0];

#define SCL4(v) v.x *= inv; v.y *= inv; v.z *= inv; v.w *= inv;
    SCL4(d0) SCL4(d1) SCL4(d2) SCL4(d3)
#undef SCL4
    p[tid] = d0; p[tid + 256] = d1; p[tid + 512] = d2; p[tid + 768] = d3;
}

// ---------------------------------------------------------------------------
// Row LayerNorm over D=1024: out = LN(X + R) * g + b   (R optional)
// ---------------------------------------------------------------------------
__global__ void __launch_bounds__(256) ln_row(
    const float* __restrict__ X, const float* __restrict__ R,
    const float* __restrict__ g, const float* __restrict__ b,
    float* __restrict__ out)
{
    __shared__ float red[256];
    const int tid = threadIdx.x;
    const size_t row = blockIdx.x;

    float4 v = ((const float4*)(X + row * DD_))[tid];
    if (R) {
        float4 r = ((const float4*)(R + row * DD_))[tid];
        v.x += r.x; v.y += r.y; v.z += r.z; v.w += r.w;
    }
    red[tid] = v.x + v.y + v.z + v.w;
    __syncthreads();
    for (int s = 128; s > 0; s >>= 1) {
        if (tid < s) red[tid] += red[tid + s];
        __syncthreads();
    }
    const float mu = red[0] * (1.0f / DD_);
    __syncthreads();

    float dx = v.x - mu, dy = v.y - mu, dz = v.z - mu, dw = v.w - mu;
    red[tid] = dx * dx + dy * dy + dz * dz + dw * dw;
    __syncthreads();
    for (int s = 128; s > 0; s >>= 1) {
        if (tid < s) red[tid] += red[tid + s];
        __syncthreads();
    }
    const float rs = rsqrtf(red[0] * (1.0f / DD_) + 1e-5f);

    float4 gg = ((const float4*)g)[tid];
    float4 bb = ((const float4*)b)[tid];
    float4 o;
    o.x = dx * rs * gg.x + bb.x;
    o.y = dy * rs * gg.y + bb.y;
    o.z = dz * rs * gg.z + bb.z;
    o.w = dw * rs * gg.w + bb.w;
    ((float4*)(out + row * DD_))[tid] = o;
}

// ---------------------------------------------------------------------------
extern "C" void kernel_launch(void* const* d_in, const int* in_sizes, int n_in,
                              void* d_out, int out_size)
{
    const float* x        = (const float*)d_in[0];
    const float* adj      = (const float*)d_in[1];
    const float* Wq       = (const float*)d_in[2];
    const float* Wk       = (const float*)d_in[3];
    const float* Wv       = (const float*)d_in[4];
    const float* Wo_w     = (const float*)d_in[5];
    const float* Wo_b     = (const float*)d_in[6];
    const float* adj_bias = (const float*)d_in[7];
    const float* ln1_g    = (const float*)d_in[8];
    const float* ln1_b    = (const float*)d_in[9];
    const float* ffn_ln_g = (const float*)d_in[10];
    const float* ffn_ln_b = (const float*)d_in[11];
    const float* ffn_w1   = (const float*)d_in[12];
    const float* ffn_b1   = (const float*)d_in[13];
    const float* ffn_w2   = (const float*)d_in[14];
    const float* ffn_b2   = (const float*)d_in[15];
    float* out = (float*)d_out;

    float* scr = nullptr;
    cudaGetSymbolAddress((void**)&scr, g_scratch);

    float* Q  = scr + 0 * SZ_ND;
    float* Kb = scr + 1 * SZ_ND;
    float* V  = scr + 2 * SZ_ND;
    float* AO = scr + 3 * SZ_ND;
    float* P  = scr + 4 * SZ_ND;
    float* Hb = scr + 5 * SZ_ND;
    float* Fb = scr + 6 * SZ_ND;
    float* S  = scr + 7 * SZ_ND;
    float* T  = S + 8 * SZ_NN;

    const int TH = 256;
    const float scale = 0.08838834764831845f;  // 128^-0.5

    // --- Q/K/V projections: (4096x1024) @ (1024x1024)
    dim3 gqkv(DD_ / BN, NN_ / BM);
    gemm_tc<false, 0><<<gqkv, TH>>>(x, Wq, Q, DD_, DD_, DD_, DD_,
                                    0, 0, 0, nullptr, nullptr, 0, nullptr, 0, 0.f, nullptr);
    gemm_tc<false, 0><<<gqkv, TH>>>(x, Wk, Kb, DD_, DD_, DD_, DD_,
                                    0, 0, 0, nullptr, nullptr, 0, nullptr, 0, 0.f, nullptr);
    gemm_tc<false, 0><<<gqkv, TH>>>(x, Wv, V, DD_, DD_, DD_, DD_,
                                    0, 0, 0, nullptr, nullptr, 0, nullptr, 0, 0.f, nullptr);

    // --- Scores: S[h] = scale * Q_h K_h^T + beta_h * adj   (batched over heads)
    dim3 gsc(NN_ / BN, NN_ / BM, HH_);
    gemm_tc<true, 4><<<gsc, TH>>>(Q, Kb, S, DH_, DD_, DD_, NN_,
                                  DH_, DH_, (long long)SZ_NN,
                                  nullptr, nullptr, 0, adj, NN_, scale, adj_bias);

    // --- Softmax over rows of each head's S
    softmax4096<<<dim3(NN_, HH_), TH>>>(S);

    // --- O_h = S[h] @ V_h   (batched over heads)
    dim3 gav(DH_ / BN, NN_ / BM, HH_);
    gemm_tc<false, 0><<<gav, TH>>>(S, V, AO, NN_, NN_, DD_, DD_,
                                   (long long)SZ_NN, DH_, DH_,
                                   nullptr, nullptr, 0, nullptr, 0, 0.f, nullptr);

    // --- Output projection with bias
    gemm_tc<false, 1><<<gqkv, TH>>>(AO, Wo_w, P, DD_, DD_, DD_, DD_,
                                    0, 0, 0, Wo_b, nullptr, 0, nullptr, 0, 0.f, nullptr);

    // --- h = LN(x + P);  f = LN(h)
    ln_row<<<NN_, TH>>>(x, P, ln1_g, ln1_b, Hb);
    ln_row<<<NN_, TH>>>(Hb, nullptr, ffn_ln_g, ffn_ln_b, Fb);

    // --- FFN1 with fused exact GELU: T = gelu(F @ W1 + b1)
    dim3 gf1(FF_ / BN, NN_ / BM);
    gemm_tc<false, 2><<<gf1, TH>>>(Fb, ffn_w1, T, DD_, DD_, FF_, FF_,
                                   0, 0, 0, ffn_b1, nullptr, 0, nullptr, 0, 0.f, nullptr);

    // --- FFN2 + bias + residual h: out = T @ W2 + b2 + h
    dim3 gf2(DD_ / BN, NN_ / BM);
    gemm_tc<false, 3><<<gf2, TH>>>(T, ffn_w2, out, FF_, FF_, DD_, DD_,
                                   0, 0, 0, ffn_b2, Hb, DD_, nullptr, 0, 0.f, nullptr);
}

// round 7
// speedup vs baseline: 2.1179x; 1.0422x over previous
#include <cuda_runtime.h>
#include <math.h>

// Problem constants
#define NN_ 4096
#define DD_ 1024
#define HH_ 8
#define DH_ 128
#define FF_ 2048   // 2*D

static const size_t SZ_ND = (size_t)NN_ * DD_;      // 4,194,304
static const size_t SZ_NF = (size_t)NN_ * FF_;      // 8,388,608

// Scratch: Q,K,V,AO,P,H,F (7*SZ_ND) | T (SZ_NF)
__device__ float g_scratch[7 * 4194304ull + 8388608ull];

// ---------------------------------------------------------------------------
// TF32 helpers
// ---------------------------------------------------------------------------
__device__ __forceinline__ unsigned f2tf(float f) {
    unsigned u;
    asm("cvt.rna.tf32.f32 %0, %1;" : "=r"(u) : "f"(f));
    return u;
}

__device__ __forceinline__ void mma_tf32(float* d, const unsigned* a, const unsigned* b) {
    asm volatile(
        "mma.sync.aligned.m16n8k8.row.col.f32.tf32.tf32.f32 "
        "{%0,%1,%2,%3}, {%4,%5,%6,%7}, {%8,%9}, {%0,%1,%2,%3};"
        : "+f"(d[0]), "+f"(d[1]), "+f"(d[2]), "+f"(d[3])
        : "r"(a[0]), "r"(a[1]), "r"(a[2]), "r"(a[3]), "r"(b[0]), "r"(b[1]));
}

// ---------------------------------------------------------------------------
// TF32 tensor-core GEMM (unchanged from R3): C = A @ B (or A @ B^T when TB)
// ---------------------------------------------------------------------------
#define BM 128
#define BN 128
#define BK 16

template <bool TB, int EPI>
__global__ void __launch_bounds__(256, 2) gemm_tc(
    const float* __restrict__ A, const float* __restrict__ B, float* __restrict__ C,
    int K, int lda, int ldb, int ldc,
    long long sA, long long sB, long long sC,
    const float* __restrict__ bias,
    const float* __restrict__ addm, int ldadd)
{
    __shared__ __align__(16) unsigned As[2][BK][BM + 8];
    __shared__ __align__(16) unsigned Bs[2][BK][BN + 8];

    const int z = blockIdx.z;
    A += (size_t)z * sA;
    B += (size_t)z * sB;
    C += (size_t)z * sC;

    const int tid  = threadIdx.x;
    const int lane = tid & 31;
    const int wid  = tid >> 5;
    const int gid  = lane >> 2;
    const int tq   = lane & 3;
    const int wm0  = (wid & 3) * 32;
    const int wn0  = (wid >> 2) * 64;
    const int row0 = blockIdx.y * BM;
    const int col0 = blockIdx.x * BN;

    const int ar  = tid & 127;
    const int ac0 = (tid >> 7) * 4;
    const int bk  = tid >> 5;
    const int bn4 = (tid & 31) * 4;

    const float* Aptr = A + (size_t)(row0 + ar) * lda + ac0;
    const float* Bptr;
    if (TB) Bptr = B + (size_t)(col0 + ar) * ldb + ac0;
    else    Bptr = B + (size_t)bk * ldb + col0 + bn4;

    float acc[2][8][4];
#pragma unroll
    for (int mt = 0; mt < 2; mt++)
#pragma unroll
        for (int nt = 0; nt < 8; nt++)
#pragma unroll
            for (int c = 0; c < 4; c++) acc[mt][nt][c] = 0.f;

    float4 aR0, aR1, bR0, bR1;

    aR0 = *(const float4*)(Aptr);
    aR1 = *(const float4*)(Aptr + 8);
    if (TB) {
        bR0 = *(const float4*)(Bptr);
        bR1 = *(const float4*)(Bptr + 8);
    } else {
        bR0 = *(const float4*)(Bptr);
        bR1 = *(const float4*)(Bptr + (size_t)8 * ldb);
    }

    auto sts = [&](int buf) {
        As[buf][ac0 + 0][ar] = f2tf(aR0.x);
        As[buf][ac0 + 1][ar] = f2tf(aR0.y);
        As[buf][ac0 + 2][ar] = f2tf(aR0.z);
        As[buf][ac0 + 3][ar] = f2tf(aR0.w);
        As[buf][ac0 + 8][ar] = f2tf(aR1.x);
        As[buf][ac0 + 9][ar] = f2tf(aR1.y);
        As[buf][ac0 + 10][ar] = f2tf(aR1.z);
        As[buf][ac0 + 11][ar] = f2tf(aR1.w);
        if (TB) {
            Bs[buf][ac0 + 0][ar] = f2tf(bR0.x);
            Bs[buf][ac0 + 1][ar] = f2tf(bR0.y);
            Bs[buf][ac0 + 2][ar] = f2tf(bR0.z);
            Bs[buf][ac0 + 3][ar] = f2tf(bR0.w);
            Bs[buf][ac0 + 8][ar] = f2tf(bR1.x);
            Bs[buf][ac0 + 9][ar] = f2tf(bR1.y);
            Bs[buf][ac0 + 10][ar] = f2tf(bR1.z);
            Bs[buf][ac0 + 11][ar] = f2tf(bR1.w);
        } else {
            uint4 u0 = make_uint4(f2tf(bR0.x), f2tf(bR0.y), f2tf(bR0.z), f2tf(bR0.w));
            uint4 u1 = make_uint4(f2tf(bR1.x), f2tf(bR1.y), f2tf(bR1.z), f2tf(bR1.w));
            *(uint4*)&Bs[buf][bk][bn4] = u0;
            *(uint4*)&Bs[buf][bk + 8][bn4] = u1;
        }
    };

    auto compute = [&](int buf) {
#pragma unroll
        for (int ks = 0; ks < 2; ks++) {
            const int kb = ks * 8;
            unsigned af[2][4], bf[8][2];
#pragma unroll
            for (int mt = 0; mt < 2; mt++) {
                const int m = wm0 + mt * 16 + gid;
                af[mt][0] = As[buf][kb + tq][m];
                af[mt][1] = As[buf][kb + tq][m + 8];
                af[mt][2] = As[buf][kb + tq + 4][m];
                af[mt][3] = As[buf][kb + tq + 4][m + 8];
            }
#pragma unroll
            for (int nt = 0; nt < 8; nt++) {
                const int n = wn0 + nt * 8 + gid;
                bf[nt][0] = Bs[buf][kb + tq][n];
                bf[nt][1] = Bs[buf][kb + tq + 4][n];
            }
#pragma unroll
            for (int mt = 0; mt < 2; mt++)
#pragma unroll
                for (int nt = 0; nt < 8; nt++)
                    mma_tf32(acc[mt][nt], af[mt], bf[nt]);
        }
    };

    int buf = 0;
    sts(0);
    __syncthreads();

    for (int k0 = BK; k0 < K; k0 += BK) {
        aR0 = *(const float4*)(Aptr + k0);
        aR1 = *(const float4*)(Aptr + k0 + 8);
        if (TB) {
            bR0 = *(const float4*)(Bptr + k0);
            bR1 = *(const float4*)(Bptr + k0 + 8);
        } else {
            bR0 = *(const float4*)(Bptr + (size_t)k0 * ldb);
            bR1 = *(const float4*)(Bptr + (size_t)(k0 + 8) * ldb);
        }
        compute(buf);
        sts(buf ^ 1);
        __syncthreads();
        buf ^= 1;
    }
    compute(buf);

#pragma unroll
    for (int mt = 0; mt < 2; mt++) {
        const int r = row0 + wm0 + mt * 16 + gid;
#pragma unroll
        for (int nt = 0; nt < 8; nt++) {
            const int c = col0 + wn0 + nt * 8 + 2 * tq;
            float v0 = acc[mt][nt][0];
            float v1 = acc[mt][nt][1];
            float v2 = acc[mt][nt][2];
            float v3 = acc[mt][nt][3];
            if (EPI == 1) {
                v0 += bias[c]; v1 += bias[c + 1];
                v2 += bias[c]; v3 += bias[c + 1];
            } else if (EPI == 2) {
                v0 += bias[c]; v1 += bias[c + 1];
                v2 += bias[c]; v3 += bias[c + 1];
                v0 = 0.5f * v0 * (1.f + erff(v0 * 0.70710678118654752f));
                v1 = 0.5f * v1 * (1.f + erff(v1 * 0.70710678118654752f));
                v2 = 0.5f * v2 * (1.f + erff(v2 * 0.70710678118654752f));
                v3 = 0.5f * v3 * (1.f + erff(v3 * 0.70710678118654752f));
            } else if (EPI == 3) {
                float2 m0 = *(const float2*)&addm[(size_t)r * ldadd + c];
                float2 m1 = *(const float2*)&addm[(size_t)(r + 8) * ldadd + c];
                v0 += bias[c] + m0.x;     v1 += bias[c + 1] + m0.y;
                v2 += bias[c] + m1.x;     v3 += bias[c + 1] + m1.y;
            }
            *(float2*)&C[(size_t)r * ldc + c] = make_float2(v0, v1);
            *(float2*)&C[(size_t)(r + 8) * ldc + c] = make_float2(v2, v3);
        }
    }
}

// ---------------------------------------------------------------------------
// Fused flash attention: per (head, 128-row Q block):
//   stream 64-key tiles; S = scale*Q K^T + beta_h*adj; online softmax; O += P V
// Writes normalized O to AO[row][h*128 .. h*128+127].
// 8 warps; each warp owns 16 q-rows (full 64 S cols, full 128 O cols).
// Dynamic smem: Qs[128][132] | Kt[128][72] | Vt[128][72] | Ps[128][68]
// ---------------------------------------------------------------------------
#define QROWS 128
#define KTILE 64
#define QS_LD 132
#define KT_LD 72
#define PS_LD 68

__global__ void __launch_bounds__(256, 1) flash_attn(
    const float* __restrict__ Q, const float* __restrict__ Km,
    const float* __restrict__ Vm, const float* __restrict__ adj,
    const float* __restrict__ adj_bias, float* __restrict__ AO, float scale)
{
    extern __shared__ unsigned sm[];
    unsigned* Qs = sm;                          // 128*132
    unsigned* Kt = Qs + QROWS * QS_LD;          // 128*72  [dh][key]
    unsigned* Vt = Kt + DH_ * KT_LD;            // 128*72  [dh][key]
    unsigned* Ps = Vt + DH_ * KT_LD;            // 128*68  [row][key]

    const int h  = blockIdx.x;
    const int q0 = blockIdx.y * QROWS;
    const int tid  = threadIdx.x;
    const int lane = tid & 31;
    const int wid  = tid >> 5;
    const int gid  = lane >> 2;
    const int tq   = lane & 3;
    const int wr0  = wid * 16;           // warp's q-row base within tile

    const float beta = adj_bias[h];

    // ---- load Q tile (once): rows q0..q0+127, dh 0..127 ----
    {
        const int r  = tid >> 1;
        const int c0 = (tid & 1) * 64;
        const float* qp = Q + (size_t)(q0 + r) * DD_ + h * DH_ + c0;
#pragma unroll
        for (int i = 0; i < 16; i++) {
            float4 v = *(const float4*)(qp + i * 4);
            unsigned* d = Qs + r * QS_LD + c0 + i * 4;
            d[0] = f2tf(v.x); d[1] = f2tf(v.y); d[2] = f2tf(v.z); d[3] = f2tf(v.w);
        }
    }

    float o[16][4];
#pragma unroll
    for (int nt = 0; nt < 16; nt++)
#pragma unroll
        for (int c = 0; c < 4; c++) o[nt][c] = 0.f;
    float m0 = -1e30f, m1 = -1e30f, l0 = 0.f, l1 = 0.f;

    // K/V load mapping: kk = tid&63 (key), dgrp = tid>>6 -> dh chunk of 32
    const int kk = tid & 63;
    const int d0 = (tid >> 6) * 32;

    for (int j = 0; j < NN_ / KTILE; j++) {
        const int kj0 = j * KTILE;
        __syncthreads();   // previous iter's Kt/Vt reads complete
        {
            const float* kp = Km + (size_t)(kj0 + kk) * DD_ + h * DH_ + d0;
            const float* vp = Vm + (size_t)(kj0 + kk) * DD_ + h * DH_ + d0;
#pragma unroll
            for (int i = 0; i < 8; i++) {
                float4 kv = *(const float4*)(kp + i * 4);
                float4 vv = *(const float4*)(vp + i * 4);
                const int d = d0 + i * 4;
                Kt[(d + 0) * KT_LD + kk] = f2tf(kv.x);
                Kt[(d + 1) * KT_LD + kk] = f2tf(kv.y);
                Kt[(d + 2) * KT_LD + kk] = f2tf(kv.z);
                Kt[(d + 3) * KT_LD + kk] = f2tf(kv.w);
                Vt[(d + 0) * KT_LD + kk] = f2tf(vv.x);
                Vt[(d + 1) * KT_LD + kk] = f2tf(vv.y);
                Vt[(d + 2) * KT_LD + kk] = f2tf(vv.z);
                Vt[(d + 3) * KT_LD + kk] = f2tf(vv.w);
            }
        }
        __syncthreads();

        // ---- S = Q Kt^T : warp rows wr0..wr0+15, cols 0..63 ----
        float s[8][4];
#pragma unroll
        for (int nt = 0; nt < 8; nt++)
#pragma unroll
            for (int c = 0; c < 4; c++) s[nt][c] = 0.f;

#pragma unroll
        for (int ks = 0; ks < 16; ks++) {
            const int k8 = ks * 8;
            unsigned af[4];
            af[0] = Qs[(wr0 + gid) * QS_LD + k8 + tq];
            af[1] = Qs[(wr0 + gid + 8) * QS_LD + k8 + tq];
            af[2] = Qs[(wr0 + gid) * QS_LD + k8 + tq + 4];
            af[3] = Qs[(wr0 + gid + 8) * QS_LD + k8 + tq + 4];
#pragma unroll
            for (int nt = 0; nt < 8; nt++) {
                unsigned bf[2];
                bf[0] = Kt[(k8 + tq) * KT_LD + nt * 8 + gid];
                bf[1] = Kt[(k8 + tq + 4) * KT_LD + nt * 8 + gid];
                mma_tf32(s[nt], af, bf);
            }
        }

        // ---- add scale + beta*adj ----
        const float* arow0 = adj + (size_t)(q0 + wr0 + gid) * NN_ + kj0;
        const float* arow1 = arow0 + (size_t)8 * NN_;
#pragma unroll
        for (int nt = 0; nt < 8; nt++) {
            const int c = nt * 8 + 2 * tq;
            float2 j0 = *(const float2*)(arow0 + c);
            float2 j1 = *(const float2*)(arow1 + c);
            s[nt][0] = s[nt][0] * scale + beta * j0.x;
            s[nt][1] = s[nt][1] * scale + beta * j0.y;
            s[nt][2] = s[nt][2] * scale + beta * j1.x;
            s[nt][3] = s[nt][3] * scale + beta * j1.y;
        }

        // ---- online softmax ----
        float mx0 = -1e30f, mx1 = -1e30f;
#pragma unroll
        for (int nt = 0; nt < 8; nt++) {
            mx0 = fmaxf(mx0, fmaxf(s[nt][0], s[nt][1]));
            mx1 = fmaxf(mx1, fmaxf(s[nt][2], s[nt][3]));
        }
        mx0 = fmaxf(mx0, __shfl_xor_sync(0xffffffffu, mx0, 1));
        mx0 = fmaxf(mx0, __shfl_xor_sync(0xffffffffu, mx0, 2));
        mx1 = fmaxf(mx1, __shfl_xor_sync(0xffffffffu, mx1, 1));
        mx1 = fmaxf(mx1, __shfl_xor_sync(0xffffffffu, mx1, 2));

        const float mn0 = fmaxf(m0, mx0);
        const float mn1 = fmaxf(m1, mx1);
        const float f0 = __expf(m0 - mn0);
        const float f1 = __expf(m1 - mn1);
        m0 = mn0; m1 = mn1;

        float sum0 = 0.f, sum1 = 0.f;
#pragma unroll
        for (int nt = 0; nt < 8; nt++) {
            s[nt][0] = __expf(s[nt][0] - mn0);
            s[nt][1] = __expf(s[nt][1] - mn0);
            s[nt][2] = __expf(s[nt][2] - mn1);
            s[nt][3] = __expf(s[nt][3] - mn1);
            sum0 += s[nt][0] + s[nt][1];
            sum1 += s[nt][2] + s[nt][3];
        }
        sum0 += __shfl_xor_sync(0xffffffffu, sum0, 1);
        sum0 += __shfl_xor_sync(0xffffffffu, sum0, 2);
        sum1 += __shfl_xor_sync(0xffffffffu, sum1, 1);
        sum1 += __shfl_xor_sync(0xffffffffu, sum1, 2);
        l0 = l0 * f0 + sum0;
        l1 = l1 * f1 + sum1;

        // rescale O
#pragma unroll
        for (int nt = 0; nt < 16; nt++) {
            o[nt][0] *= f0; o[nt][1] *= f0;
            o[nt][2] *= f1; o[nt][3] *= f1;
        }

        // ---- P to smem (warp-private region) ----
#pragma unroll
        for (int nt = 0; nt < 8; nt++) {
            const int c = nt * 8 + 2 * tq;
            unsigned* p0 = Ps + (wr0 + gid) * PS_LD + c;
            unsigned* p1 = Ps + (wr0 + gid + 8) * PS_LD + c;
            p0[0] = f2tf(s[nt][0]); p0[1] = f2tf(s[nt][1]);
            p1[0] = f2tf(s[nt][2]); p1[1] = f2tf(s[nt][3]);
        }
        __syncwarp();

        // ---- O += P @ V : k over 64 keys, n over 128 dh ----
#pragma unroll
        for (int ks = 0; ks < 8; ks++) {
            const int k8 = ks * 8;
            unsigned af[4];
            af[0] = Ps[(wr0 + gid) * PS_LD + k8 + tq];
            af[1] = Ps[(wr0 + gid + 8) * PS_LD + k8 + tq];
            af[2] = Ps[(wr0 + gid) * PS_LD + k8 + tq + 4];
            af[3] = Ps[(wr0 + gid + 8) * PS_LD + k8 + tq + 4];
#pragma unroll
            for (int nt = 0; nt < 16; nt++) {
                unsigned bf[2];
                bf[0] = Vt[(nt * 8 + gid) * KT_LD + k8 + tq];
                bf[1] = Vt[(nt * 8 + gid) * KT_LD + k8 + tq + 4];
                mma_tf32(o[nt], af, bf);
            }
        }
        __syncwarp();
    }

    // ---- normalize and write out ----
    const float inv0 = 1.0f / l0;
    const float inv1 = 1.0f / l1;
    float* o0 = AO + (size_t)(q0 + wr0 + gid) * DD_ + h * DH_;
    float* o1 = o0 + (size_t)8 * DD_;
#pragma unroll
    for (int nt = 0; nt < 16; nt++) {
        const int c = nt * 8 + 2 * tq;
        *(float2*)(o0 + c) = make_float2(o[nt][0] * inv0, o[nt][1] * inv0);
        *(float2*)(o1 + c) = make_float2(o[nt][2] * inv1, o[nt][3] * inv1);
    }
}

// ---------------------------------------------------------------------------
// Row LayerNorm over D=1024: out = LN(X + R) * g + b   (R optional)
// ---------------------------------------------------------------------------
__global__ void __launch_bounds__(256) ln_row(
    const float* __restrict__ X, const float* __restrict__ R,
    const float* __restrict__ g, const float* __restrict__ b,
    float* __restrict__ out)
{
    __shared__ float red[256];
    const int tid = threadIdx.x;
    const size_t row = blockIdx.x;

    float4 v = ((const float4*)(X + row * DD_))[tid];
    if (R) {
        float4 r = ((const float4*)(R + row * DD_))[tid];
        v.x += r.x; v.y += r.y; v.z += r.z; v.w += r.w;
    }
    red[tid] = v.x + v.y + v.z + v.w;
    __syncthreads();
    for (int s = 128; s > 0; s >>= 1) {
        if (tid < s) red[tid] += red[tid + s];
        __syncthreads();
    }
    const float mu = red[0] * (1.0f / DD_);
    __syncthreads();

    float dx = v.x - mu, dy = v.y - mu, dz = v.z - mu, dw = v.w - mu;
    red[tid] = dx * dx + dy * dy + dz * dz + dw * dw;
    __syncthreads();
    for (int s = 128; s > 0; s >>= 1) {
        if (tid < s) red[tid] += red[tid + s];
        __syncthreads();
    }
    const float rs = rsqrtf(red[0] * (1.0f / DD_) + 1e-5f);

    float4 gg = ((const float4*)g)[tid];
    float4 bb = ((const float4*)b)[tid];
    float4 o;
    o.x = dx * rs * gg.x + bb.x;
    o.y = dy * rs * gg.y + bb.y;
    o.z = dz * rs * gg.z + bb.z;
    o.w = dw * rs * gg.w + bb.w;
    ((float4*)(out + row * DD_))[tid] = o;
}

// ---------------------------------------------------------------------------
extern "C" void kernel_launch(void* const* d_in, const int* in_sizes, int n_in,
                              void* d_out, int out_size)
{
    const float* x        = (const float*)d_in[0];
    const float* adj      = (const float*)d_in[1];
    const float* Wq       = (const float*)d_in[2];
    const float* Wk       = (const float*)d_in[3];
    const float* Wv       = (const float*)d_in[4];
    const float* Wo_w     = (const float*)d_in[5];
    const float* Wo_b     = (const float*)d_in[6];
    const float* adj_bias = (const float*)d_in[7];
    const float* ln1_g    = (const float*)d_in[8];
    const float* ln1_b    = (const float*)d_in[9];
    const float* ffn_ln_g = (const float*)d_in[10];
    const float* ffn_ln_b = (const float*)d_in[11];
    const float* ffn_w1   = (const float*)d_in[12];
    const float* ffn_b1   = (const float*)d_in[13];
    const float* ffn_w2   = (const float*)d_in[14];
    const float* ffn_b2   = (const float*)d_in[15];
    float* out = (float*)d_out;

    float* scr = nullptr;
    cudaGetSymbolAddress((void**)&scr, g_scratch);

    float* Q  = scr + 0 * SZ_ND;
    float* Kb = scr + 1 * SZ_ND;
    float* V  = scr + 2 * SZ_ND;
    float* AO = scr + 3 * SZ_ND;
    float* P  = scr + 4 * SZ_ND;
    float* Hb = scr + 5 * SZ_ND;
    float* Fb = scr + 6 * SZ_ND;
    float* T  = scr + 7 * SZ_ND;

    const int TH = 256;
    const float scale = 0.08838834764831845f;  // 128^-0.5

    // flash attention dynamic smem: (128*132 + 2*128*72 + 128*68) * 4 bytes
    const int FLASH_SMEM = (QROWS * QS_LD + 2 * DH_ * KT_LD + QROWS * PS_LD) * 4;
    static int smem_set = 0;
    if (!smem_set) {
        cudaFuncSetAttribute(flash_attn, cudaFuncAttributeMaxDynamicSharedMemorySize, FLASH_SMEM);
        smem_set = 1;
    }

    // --- Q/K/V projections
    dim3 gqkv(DD_ / BN, NN_ / BM);
    gemm_tc<false, 0><<<gqkv, TH>>>(x, Wq, Q, DD_, DD_, DD_, DD_,
                                    0, 0, 0, nullptr, nullptr, 0);
    gemm_tc<false, 0><<<gqkv, TH>>>(x, Wk, Kb, DD_, DD_, DD_, DD_,
                                    0, 0, 0, nullptr, nullptr, 0);
    gemm_tc<false, 0><<<gqkv, TH>>>(x, Wv, V, DD_, DD_, DD_, DD_,
                                    0, 0, 0, nullptr, nullptr, 0);

    // --- Fused attention (scores + adj bias + softmax + @V)
    flash_attn<<<dim3(HH_, NN_ / QROWS), TH, FLASH_SMEM>>>(Q, Kb, V, adj, adj_bias, AO, scale);

    // --- Output projection with bias
    gemm_tc<false, 1><<<gqkv, TH>>>(AO, Wo_w, P, DD_, DD_, DD_, DD_,
                                    0, 0, 0, Wo_b, nullptr, 0);

    // --- h = LN(x + P);  f = LN(h)
    ln_row<<<NN_, TH>>>(x, P, ln1_g, ln1_b, Hb);
    ln_row<<<NN_, TH>>>(Hb, nullptr, ffn_ln_g, ffn_ln_b, Fb);

    // --- FFN1 with fused exact GELU
    dim3 gf1(FF_ / BN, NN_ / BM);
    gemm_tc<false, 2><<<gf1, TH>>>(Fb, ffn_w1, T, DD_, DD_, FF_, FF_,
                                   0, 0, 0, ffn_b1, nullptr, 0);

    // --- FFN2 + bias + residual h
    dim3 gf2(DD_ / BN, NN_ / BM);
    gemm_tc<false, 3><<<gf2, TH>>>(T, ffn_w2, out, FF_, FF_, DD_, DD_,
                                   0, 0, 0, ffn_b2, Hb, DD_);
}

// round 10
// speedup vs baseline: 3.0837x; 1.4560x over previous
#include <cuda_runtime.h>
#include <math.h>

// Problem constants
#define NN_ 4096
#define DD_ 1024
#define HH_ 8
#define DH_ 128
#define FF_ 2048   // 2*D

static const size_t SZ_ND = (size_t)NN_ * DD_;      // 4,194,304
static const size_t SZ_NF = (size_t)NN_ * FF_;      // 8,388,608

// Scratch: Q,K,V,AO,P,H,F (7*SZ_ND) | T (SZ_NF)
__device__ float g_scratch[7 * 4194304ull + 8388608ull];

// ---------------------------------------------------------------------------
// TF32 + cp.async helpers
// ---------------------------------------------------------------------------
__device__ __forceinline__ unsigned f2tf(float f) {
    unsigned u;
    asm("cvt.rna.tf32.f32 %0, %1;" : "=r"(u) : "f"(f));
    return u;
}

__device__ __forceinline__ void mma_tf32(float* d, const unsigned* a, const unsigned* b) {
    asm volatile(
        "mma.sync.aligned.m16n8k8.row.col.f32.tf32.tf32.f32 "
        "{%0,%1,%2,%3}, {%4,%5,%6,%7}, {%8,%9}, {%0,%1,%2,%3};"
        : "+f"(d[0]), "+f"(d[1]), "+f"(d[2]), "+f"(d[3])
        : "r"(a[0]), "r"(a[1]), "r"(a[2]), "r"(a[3]), "r"(b[0]), "r"(b[1]));
}

__device__ __forceinline__ unsigned sm_u32(const void* p) {
    return (unsigned)__cvta_generic_to_shared(p);
}
#define CPA16(s, g) asm volatile("cp.async.cg.shared.global [%0], [%1], 16;" :: "r"(s), "l"(g))
#define CPCOMMIT()  asm volatile("cp.async.commit_group;")
#define CPWAIT(n)   asm volatile("cp.async.wait_group %0;" :: "n"(n))

// ---------------------------------------------------------------------------
// TF32 tensor-core GEMM v2: C = A @ B.  128x128 tile, BK=32, 2-stage cp.async.
// Raw fp32 in smem; tf32 conversion at fragment load.
// As stride 36 (banks gid*4+tq), Bs stride 136 (banks tq*8+gid) -> conflict-free.
// EPI: 0 = none, 1 = +bias[col], 2 = gelu(+bias), 3 = +bias + addm
// ---------------------------------------------------------------------------
#define BM 128
#define BN 128
#define GBK 32
#define A_LD 36
#define B_LD 136
#define A_SZ (BM * A_LD)
#define B_SZ (GBK * B_LD)

template <int EPI>
__global__ void __launch_bounds__(256, 2) gemm_tc(
    const float* __restrict__ A, const float* __restrict__ B, float* __restrict__ C,
    int K, int lda, int ldb, int ldc,
    const float* __restrict__ bias,
    const float* __restrict__ addm, int ldadd)
{
    extern __shared__ float smg[];
    float* As = smg;               // 2 stages x 128x36
    float* Bs = smg + 2 * A_SZ;    // 2 stages x 32x136

    const int tid  = threadIdx.x;
    const int lane = tid & 31;
    const int wid  = tid >> 5;
    const int gid  = lane >> 2;
    const int tq   = lane & 3;
    const int wm0  = (wid & 3) * 32;
    const int wn0  = (wid >> 2) * 64;
    const int row0 = blockIdx.y * BM;
    const int col0 = blockIdx.x * BN;

    auto issue = [&](int st, int k0) {
        float* ad = As + st * A_SZ;
        float* bd = Bs + st * B_SZ;
#pragma unroll
        for (int i = 0; i < 4; i++) {
            int c = tid + i * 256;
            int row = c >> 3, ko = (c & 7) * 4;
            CPA16(sm_u32(ad + row * A_LD + ko), A + (size_t)(row0 + row) * lda + k0 + ko);
        }
#pragma unroll
        for (int i = 0; i < 4; i++) {
            int c = tid + i * 256;
            int row = c >> 5, no = (c & 31) * 4;
            CPA16(sm_u32(bd + row * B_LD + no), B + (size_t)(k0 + row) * ldb + col0 + no);
        }
        CPCOMMIT();
    };

    float acc[2][8][4];
#pragma unroll
    for (int mt = 0; mt < 2; mt++)
#pragma unroll
        for (int nt = 0; nt < 8; nt++)
#pragma unroll
            for (int c = 0; c < 4; c++) acc[mt][nt][c] = 0.f;

    const int KT = K / GBK;
    issue(0, 0);

    for (int it = 0; it < KT; it++) {
        if (it + 1 < KT) { issue((it + 1) & 1, (it + 1) * GBK); CPWAIT(1); }
        else             { CPWAIT(0); }
        __syncthreads();

        const float* Ab = As + (it & 1) * A_SZ;
        const float* Bb = Bs + (it & 1) * B_SZ;
#pragma unroll
        for (int ks = 0; ks < 4; ks++) {
            const int k8 = ks * 8;
            unsigned af[2][4], bf[8][2];
#pragma unroll
            for (int mt = 0; mt < 2; mt++) {
                const int m = wm0 + mt * 16 + gid;
                af[mt][0] = f2tf(Ab[(m) * A_LD + k8 + tq]);
                af[mt][1] = f2tf(Ab[(m + 8) * A_LD + k8 + tq]);
                af[mt][2] = f2tf(Ab[(m) * A_LD + k8 + tq + 4]);
                af[mt][3] = f2tf(Ab[(m + 8) * A_LD + k8 + tq + 4]);
            }
#pragma unroll
            for (int nt = 0; nt < 8; nt++) {
                const int n = wn0 + nt * 8 + gid;
                bf[nt][0] = f2tf(Bb[(k8 + tq) * B_LD + n]);
                bf[nt][1] = f2tf(Bb[(k8 + tq + 4) * B_LD + n]);
            }
#pragma unroll
            for (int mt = 0; mt < 2; mt++)
#pragma unroll
                for (int nt = 0; nt < 8; nt++)
                    mma_tf32(acc[mt][nt], af[mt], bf[nt]);
        }
        __syncthreads();
    }

    // -------- epilogue --------
#pragma unroll
    for (int mt = 0; mt < 2; mt++) {
        const int r = row0 + wm0 + mt * 16 + gid;
#pragma unroll
        for (int nt = 0; nt < 8; nt++) {
            const int c = col0 + wn0 + nt * 8 + 2 * tq;
            float v0 = acc[mt][nt][0];
            float v1 = acc[mt][nt][1];
            float v2 = acc[mt][nt][2];
            float v3 = acc[mt][nt][3];
            if (EPI == 1) {
                v0 += bias[c]; v1 += bias[c + 1];
                v2 += bias[c]; v3 += bias[c + 1];
            } else if (EPI == 2) {
                v0 += bias[c]; v1 += bias[c + 1];
                v2 += bias[c]; v3 += bias[c + 1];
                v0 = 0.5f * v0 * (1.f + erff(v0 * 0.70710678118654752f));
                v1 = 0.5f * v1 * (1.f + erff(v1 * 0.70710678118654752f));
                v2 = 0.5f * v2 * (1.f + erff(v2 * 0.70710678118654752f));
                v3 = 0.5f * v3 * (1.f + erff(v3 * 0.70710678118654752f));
            } else if (EPI == 3) {
                float2 m0 = *(const float2*)&addm[(size_t)r * ldadd + c];
                float2 m1 = *(const float2*)&addm[(size_t)(r + 8) * ldadd + c];
                v0 += bias[c] + m0.x;     v1 += bias[c + 1] + m0.y;
                v2 += bias[c] + m1.x;     v3 += bias[c + 1] + m1.y;
            }
            *(float2*)&C[(size_t)r * ldc + c] = make_float2(v0, v1);
            *(float2*)&C[(size_t)(r + 8) * ldc + c] = make_float2(v2, v3);
        }
    }
}

// ---------------------------------------------------------------------------
// Flash attention v2: Q A-fragments in registers; K/V 2-stage cp.async;
// P fragment built via warp shuffles (no smem round-trip).
// Grid (H, N/128). 8 warps, each owns 16 q-rows.
// smem: Kst 2 x [64][132] | Vst 2 x [64][136]  (134 KB)
// ---------------------------------------------------------------------------
#define QROWS 128
#define KTILE 64
#define K_LDS 132
#define V_LDS 136
#define K_SZ (KTILE * K_LDS)
#define V_SZ (KTILE * V_LDS)

__global__ void __launch_bounds__(256, 1) flash_attn(
    const float* __restrict__ Q, const float* __restrict__ Km,
    const float* __restrict__ Vm, const float* __restrict__ adj,
    const float* __restrict__ adj_bias, float* __restrict__ AO, float scale)
{
    extern __shared__ float sm[];
    float* Kst = sm;               // 2 x 64x132  [key][dh]
    float* Vst = sm + 2 * K_SZ;    // 2 x 64x136  [key][dh]

    const int h  = blockIdx.x;
    const int q0 = blockIdx.y * QROWS;
    const int tid  = threadIdx.x;
    const int lane = tid & 31;
    const int wid  = tid >> 5;
    const int gid  = lane >> 2;
    const int tq   = lane & 3;
    const int wr0  = wid * 16;

    const float beta = adj_bias[h];

    auto issue = [&](int st, int j) {
        const float* kb = Km + (size_t)(j * KTILE) * DD_ + h * DH_;
        const float* vb = Vm + (size_t)(j * KTILE) * DD_ + h * DH_;
        float* kd = Kst + st * K_SZ;
        float* vd = Vst + st * V_SZ;
#pragma unroll
        for (int i = 0; i < 8; i++) {
            int c = tid + i * 256;
            int row = c >> 5, off = (c & 31) * 4;
            CPA16(sm_u32(kd + row * K_LDS + off), kb + (size_t)row * DD_ + off);
            CPA16(sm_u32(vd + row * V_LDS + off), vb + (size_t)row * DD_ + off);
        }
        CPCOMMIT();
    };

    // ---- Q A-fragments in registers (warp-private rows) ----
    unsigned qa[16][4];
    {
        const float* qb0 = Q + (size_t)(q0 + wr0 + gid) * DD_ + h * DH_;
        const float* qb8 = qb0 + (size_t)8 * DD_;
#pragma unroll
        for (int ks = 0; ks < 16; ks++) {
            qa[ks][0] = f2tf(qb0[ks * 8 + tq]);
            qa[ks][1] = f2tf(qb8[ks * 8 + tq]);
            qa[ks][2] = f2tf(qb0[ks * 8 + tq + 4]);
            qa[ks][3] = f2tf(qb8[ks * 8 + tq + 4]);
        }
    }

    float o[16][4];
#pragma unroll
    for (int nt = 0; nt < 16; nt++)
#pragma unroll
        for (int c = 0; c < 4; c++) o[nt][c] = 0.f;
    float m0 = -1e30f, m1 = -1e30f, l0 = 0.f, l1 = 0.f;

    const int NT = NN_ / KTILE;
    issue(0, 0);

    for (int j = 0; j < NT; j++) {
        if (j + 1 < NT) { issue((j + 1) & 1, j + 1); CPWAIT(1); }
        else            { CPWAIT(0); }
        __syncthreads();

        const float* Kb = Kst + (j & 1) * K_SZ;
        const float* Vb = Vst + (j & 1) * V_SZ;

        // ---- S = Q K^T ----
        float s[8][4];
#pragma unroll
        for (int nt = 0; nt < 8; nt++)
#pragma unroll
            for (int c = 0; c < 4; c++) s[nt][c] = 0.f;

#pragma unroll
        for (int ks = 0; ks < 16; ks++) {
            const int k8 = ks * 8;
#pragma unroll
            for (int nt = 0; nt < 8; nt++) {
                unsigned bf[2];
                bf[0] = f2tf(Kb[(nt * 8 + gid) * K_LDS + k8 + tq]);
                bf[1] = f2tf(Kb[(nt * 8 + gid) * K_LDS + k8 + tq + 4]);
                mma_tf32(s[nt], qa[ks], bf);
            }
        }

        // ---- scale + beta*adj ----
        const int kj0 = j * KTILE;
        const float* arow0 = adj + (size_t)(q0 + wr0 + gid) * NN_ + kj0;
        const float* arow1 = arow0 + (size_t)8 * NN_;
#pragma unroll
        for (int nt = 0; nt < 8; nt++) {
            const int c = nt * 8 + 2 * tq;
            float2 j0 = *(const float2*)(arow0 + c);
            float2 j1 = *(const float2*)(arow1 + c);
            s[nt][0] = s[nt][0] * scale + beta * j0.x;
            s[nt][1] = s[nt][1] * scale + beta * j0.y;
            s[nt][2] = s[nt][2] * scale + beta * j1.x;
            s[nt][3] = s[nt][3] * scale + beta * j1.y;
        }

        // ---- online softmax ----
        float mx0 = -1e30f, mx1 = -1e30f;
#pragma unroll
        for (int nt = 0; nt < 8; nt++) {
            mx0 = fmaxf(mx0, fmaxf(s[nt][0], s[nt][1]));
            mx1 = fmaxf(mx1, fmaxf(s[nt][2], s[nt][3]));
        }
        mx0 = fmaxf(mx0, __shfl_xor_sync(0xffffffffu, mx0, 1));
        mx0 = fmaxf(mx0, __shfl_xor_sync(0xffffffffu, mx0, 2));
        mx1 = fmaxf(mx1, __shfl_xor_sync(0xffffffffu, mx1, 1));
        mx1 = fmaxf(mx1, __shfl_xor_sync(0xffffffffu, mx1, 2));

        const float mn0 = fmaxf(m0, mx0);
        const float mn1 = fmaxf(m1, mx1);
        const float f0 = __expf(m0 - mn0);
        const float f1 = __expf(m1 - mn1);
        m0 = mn0; m1 = mn1;

        float sum0 = 0.f, sum1 = 0.f;
#pragma unroll
        for (int nt = 0; nt < 8; nt++) {
            s[nt][0] = __expf(s[nt][0] - mn0);
            s[nt][1] = __expf(s[nt][1] - mn0);
            s[nt][2] = __expf(s[nt][2] - mn1);
            s[nt][3] = __expf(s[nt][3] - mn1);
            sum0 += s[nt][0] + s[nt][1];
            sum1 += s[nt][2] + s[nt][3];
        }
        sum0 += __shfl_xor_sync(0xffffffffu, sum0, 1);
        sum0 += __shfl_xor_sync(0xffffffffu, sum0, 2);
        sum1 += __shfl_xor_sync(0xffffffffu, sum1, 1);
        sum1 += __shfl_xor_sync(0xffffffffu, sum1, 2);
        l0 = l0 * f0 + sum0;
        l1 = l1 * f1 + sum1;

#pragma unroll
        for (int nt = 0; nt < 16; nt++) {
            o[nt][0] *= f0; o[nt][1] *= f0;
            o[nt][2] *= f1; o[nt][3] *= f1;
        }

        // ---- O += P @ V : P A-fragments via shuffles ----
        const int src0 = (lane & 28) | (tq >> 1);
        const int src1 = src0 + 2;
        const bool odd = (tq & 1);
#pragma unroll
        for (int kt = 0; kt < 8; kt++) {
            float e0 = __shfl_sync(0xffffffffu, s[kt][0], src0);
            float e1 = __shfl_sync(0xffffffffu, s[kt][1], src0);
            float e2 = __shfl_sync(0xffffffffu, s[kt][2], src0);
            float e3 = __shfl_sync(0xffffffffu, s[kt][3], src0);
            float g0 = __shfl_sync(0xffffffffu, s[kt][0], src1);
            float g1 = __shfl_sync(0xffffffffu, s[kt][1], src1);
            float g2 = __shfl_sync(0xffffffffu, s[kt][2], src1);
            float g3 = __shfl_sync(0xffffffffu, s[kt][3], src1);
            unsigned af[4];
            af[0] = f2tf(odd ? e1 : e0);
            af[1] = f2tf(odd ? e3 : e2);
            af[2] = f2tf(odd ? g1 : g0);
            af[3] = f2tf(odd ? g3 : g2);
            const int k8 = kt * 8;
#pragma unroll
            for (int nt = 0; nt < 16; nt++) {
                unsigned bf[2];
                bf[0] = f2tf(Vb[(k8 + tq) * V_LDS + nt * 8 + gid]);
                bf[1] = f2tf(Vb[(k8 + tq + 4) * V_LDS + nt * 8 + gid]);
                mma_tf32(o[nt], af, bf);
            }
        }
        __syncthreads();
    }

    // ---- normalize and write out ----
    const float inv0 = 1.0f / l0;
    const float inv1 = 1.0f / l1;
    float* o0 = AO + (size_t)(q0 + wr0 + gid) * DD_ + h * DH_;
    float* o1 = o0 + (size_t)8 * DD_;
#pragma unroll
    for (int nt = 0; nt < 16; nt++) {
        const int c = nt * 8 + 2 * tq;
        *(float2*)(o0 + c) = make_float2(o[nt][0] * inv0, o[nt][1] * inv0);
        *(float2*)(o1 + c) = make_float2(o[nt][2] * inv1, o[nt][3] * inv1);
    }
}

// ---------------------------------------------------------------------------
// Row LayerNorm over D=1024: out = LN(X + R) * g + b   (R optional)
// ---------------------------------------------------------------------------
__global__ void __launch_bounds__(256) ln_row(
    const float* __restrict__ X, const float* __restrict__ R,
    const float* __restrict__ g, const float* __restrict__ b,
    float* __restrict__ out)
{
    __shared__ float red[256];
    const int tid = threadIdx.x;
    const size_t row = blockIdx.x;

    float4 v = ((const float4*)(X + row * DD_))[tid];
    if (R) {
        float4 r = ((const float4*)(R + row * DD_))[tid];
        v.x += r.x; v.y += r.y; v.z += r.z; v.w += r.w;
    }
    red[tid] = v.x + v.y + v.z + v.w;
    __syncthreads();
    for (int s = 128; s > 0; s >>= 1) {
        if (tid < s) red[tid] += red[tid + s];
        __syncthreads();
    }
    const float mu = red[0] * (1.0f / DD_);
    __syncthreads();

    float dx = v.x - mu, dy = v.y - mu, dz = v.z - mu, dw = v.w - mu;
    red[tid] = dx * dx + dy * dy + dz * dz + dw * dw;
    __syncthreads();
    for (int s = 128; s > 0; s >>= 1) {
        if (tid < s) red[tid] += red[tid + s];
        __syncthreads();
    }
    const float rs = rsqrtf(red[0] * (1.0f / DD_) + 1e-5f);

    float4 gg = ((const float4*)g)[tid];
    float4 bb = ((const float4*)b)[tid];
    float4 o;
    o.x = dx * rs * gg.x + bb.x;
    o.y = dy * rs * gg.y + bb.y;
    o.z = dz * rs * gg.z + bb.z;
    o.w = dw * rs * gg.w + bb.w;
    ((float4*)(out + row * DD_))[tid] = o;
}

// ---------------------------------------------------------------------------
extern "C" void kernel_launch(void* const* d_in, const int* in_sizes, int n_in,
                              void* d_out, int out_size)
{
    const float* x        = (const float*)d_in[0];
    const float* adj      = (const float*)d_in[1];
    const float* Wq       = (const float*)d_in[2];
    const float* Wk       = (const float*)d_in[3];
    const float* Wv       = (const float*)d_in[4];
    const float* Wo_w     = (const float*)d_in[5];
    const float* Wo_b     = (const float*)d_in[6];
    const float* adj_bias = (const float*)d_in[7];
    const float* ln1_g    = (const float*)d_in[8];
    const float* ln1_b    = (const float*)d_in[9];
    const float* ffn_ln_g = (const float*)d_in[10];
    const float* ffn_ln_b = (const float*)d_in[11];
    const float* ffn_w1   = (const float*)d_in[12];
    const float* ffn_b1   = (const float*)d_in[13];
    const float* ffn_w2   = (const float*)d_in[14];
    const float* ffn_b2   = (const float*)d_in[15];
    float* out = (float*)d_out;

    float* scr = nullptr;
    cudaGetSymbolAddress((void**)&scr, g_scratch);

    float* Q  = scr + 0 * SZ_ND;
    float* Kb = scr + 1 * SZ_ND;
    float* V  = scr + 2 * SZ_ND;
    float* AO = scr + 3 * SZ_ND;
    float* P  = scr + 4 * SZ_ND;
    float* Hb = scr + 5 * SZ_ND;
    float* Fb = scr + 6 * SZ_ND;
    float* T  = scr + 7 * SZ_ND;

    const int TH = 256;
    const float scale = 0.08838834764831845f;  // 128^-0.5

    const int GEMM_SMEM  = (2 * A_SZ + 2 * B_SZ) * 4;                  // 71,680 B
    const int FLASH_SMEM = (2 * K_SZ + 2 * V_SZ) * 4;                  // 137,216 B
    static int attr_set = 0;
    if (!attr_set) {
        cudaFuncSetAttribute(gemm_tc<0>, cudaFuncAttributeMaxDynamicSharedMemorySize, GEMM_SMEM);
        cudaFuncSetAttribute(gemm_tc<1>, cudaFuncAttributeMaxDynamicSharedMemorySize, GEMM_SMEM);
        cudaFuncSetAttribute(gemm_tc<2>, cudaFuncAttributeMaxDynamicSharedMemorySize, GEMM_SMEM);
        cudaFuncSetAttribute(gemm_tc<3>, cudaFuncAttributeMaxDynamicSharedMemorySize, GEMM_SMEM);
        cudaFuncSetAttribute(flash_attn, cudaFuncAttributeMaxDynamicSharedMemorySize, FLASH_SMEM);
        attr_set = 1;
    }

    // --- Q/K/V projections
    dim3 gqkv(DD_ / BN, NN_ / BM);
    gemm_tc<0><<<gqkv, TH, GEMM_SMEM>>>(x, Wq, Q, DD_, DD_, DD_, DD_, nullptr, nullptr, 0);
    gemm_tc<0><<<gqkv, TH, GEMM_SMEM>>>(x, Wk, Kb, DD_, DD_, DD_, DD_, nullptr, nullptr, 0);
    gemm_tc<0><<<gqkv, TH, GEMM_SMEM>>>(x, Wv, V, DD_, DD_, DD_, DD_, nullptr, nullptr, 0);

    // --- Fused attention (scores + adj bias + softmax + @V)
    flash_attn<<<dim3(HH_, NN_ / QROWS), TH, FLASH_SMEM>>>(Q, Kb, V, adj, adj_bias, AO, scale);

    // --- Output projection with bias
    gemm_tc<1><<<gqkv, TH, GEMM_SMEM>>>(AO, Wo_w, P, DD_, DD_, DD_, DD_, Wo_b, nullptr, 0);

    // --- h = LN(x + P);  f = LN(h)
    ln_row<<<NN_, TH>>>(x, P, ln1_g, ln1_b, Hb);
    ln_row<<<NN_, TH>>>(Hb, nullptr, ffn_ln_g, ffn_ln_b, Fb);

    // --- FFN1 with fused exact GELU
    dim3 gf1(FF_ / BN, NN_ / BM);
    gemm_tc<2><<<gf1, TH, GEMM_SMEM>>>(Fb, ffn_w1, T, DD_, DD_, FF_, FF_, ffn_b1, nullptr, 0);

    // --- FFN2 + bias + residual h
    dim3 gf2(DD_ / BN, NN_ / BM);
    gemm_tc<3><<<gf2, TH, GEMM_SMEM>>>(T, ffn_w2, out, FF_, FF_, DD_, DD_, ffn_b2, Hb, DD_);
}

// round 11
// speedup vs baseline: 3.2591x; 1.0569x over previous
#include <cuda_runtime.h>
#include <math.h>

// Problem constants
#define NN_ 4096
#define DD_ 1024
#define HH_ 8
#define DH_ 128
#define FF_ 2048   // 2*D

static const size_t SZ_ND = (size_t)NN_ * DD_;      // 4,194,304
static const size_t SZ_NF = (size_t)NN_ * FF_;      // 8,388,608

// Scratch: Q,K,V,AO,P,H,F (7*SZ_ND) | T (SZ_NF)
__device__ float g_scratch[7 * 4194304ull + 8388608ull];

// ---------------------------------------------------------------------------
// TF32 + cp.async helpers
// ---------------------------------------------------------------------------
__device__ __forceinline__ unsigned f2tf(float f) {
    unsigned u;
    asm("cvt.rna.tf32.f32 %0, %1;" : "=r"(u) : "f"(f));
    return u;
}

__device__ __forceinline__ void mma_tf32(float* d, const unsigned* a, const unsigned* b) {
    asm volatile(
        "mma.sync.aligned.m16n8k8.row.col.f32.tf32.tf32.f32 "
        "{%0,%1,%2,%3}, {%4,%5,%6,%7}, {%8,%9}, {%0,%1,%2,%3};"
        : "+f"(d[0]), "+f"(d[1]), "+f"(d[2]), "+f"(d[3])
        : "r"(a[0]), "r"(a[1]), "r"(a[2]), "r"(a[3]), "r"(b[0]), "r"(b[1]));
}

__device__ __forceinline__ unsigned sm_u32(const void* p) {
    return (unsigned)__cvta_generic_to_shared(p);
}
#define CPA16(s, g) asm volatile("cp.async.cg.shared.global [%0], [%1], 16;" :: "r"(s), "l"(g))
#define CPCOMMIT()  asm volatile("cp.async.commit_group;")
#define CPWAIT(n)   asm volatile("cp.async.wait_group %0;" :: "n"(n))

// ---------------------------------------------------------------------------
// TF32 tensor-core GEMM: C = A @ B.  128x128 tile, BK=32, 2-stage cp.async.
// Raw fp32 in smem; tf32 conversion at fragment load.
// EPI: 0 = none, 1 = +bias[col], 2 = gelu(+bias), 3 = +bias + addm
// TFOUT: store outputs pre-rounded to tf32 (consumer skips cvt).
// ---------------------------------------------------------------------------
#define BM 128
#define BN 128
#define GBK 32
#define A_LD 36
#define B_LD 136
#define A_SZ (BM * A_LD)
#define B_SZ (GBK * B_LD)

template <int EPI, bool TFOUT>
__global__ void __launch_bounds__(256, 2) gemm_tc(
    const float* __restrict__ A, const float* __restrict__ B, float* __restrict__ C,
    int K, int lda, int ldb, int ldc,
    const float* __restrict__ bias,
    const float* __restrict__ addm, int ldadd)
{
    extern __shared__ float smg[];
    float* As = smg;               // 2 stages x 128x36
    float* Bs = smg + 2 * A_SZ;    // 2 stages x 32x136

    const int tid  = threadIdx.x;
    const int lane = tid & 31;
    const int wid  = tid >> 5;
    const int gid  = lane >> 2;
    const int tq   = lane & 3;
    const int wm0  = (wid & 3) * 32;
    const int wn0  = (wid >> 2) * 64;
    const int row0 = blockIdx.y * BM;
    const int col0 = blockIdx.x * BN;

    auto issue = [&](int st, int k0) {
        float* ad = As + st * A_SZ;
        float* bd = Bs + st * B_SZ;
#pragma unroll
        for (int i = 0; i < 4; i++) {
            int c = tid + i * 256;
            int row = c >> 3, ko = (c & 7) * 4;
            CPA16(sm_u32(ad + row * A_LD + ko), A + (size_t)(row0 + row) * lda + k0 + ko);
        }
#pragma unroll
        for (int i = 0; i < 4; i++) {
            int c = tid + i * 256;
            int row = c >> 5, no = (c & 31) * 4;
            CPA16(sm_u32(bd + row * B_LD + no), B + (size_t)(k0 + row) * ldb + col0 + no);
        }
        CPCOMMIT();
    };

    float acc[2][8][4];
#pragma unroll
    for (int mt = 0; mt < 2; mt++)
#pragma unroll
        for (int nt = 0; nt < 8; nt++)
#pragma unroll
            for (int c = 0; c < 4; c++) acc[mt][nt][c] = 0.f;

    const int KT = K / GBK;
    issue(0, 0);

    for (int it = 0; it < KT; it++) {
        if (it + 1 < KT) { issue((it + 1) & 1, (it + 1) * GBK); CPWAIT(1); }
        else             { CPWAIT(0); }
        __syncthreads();

        const float* Ab = As + (it & 1) * A_SZ;
        const float* Bb = Bs + (it & 1) * B_SZ;
#pragma unroll
        for (int ks = 0; ks < 4; ks++) {
            const int k8 = ks * 8;
            unsigned af[2][4], bf[8][2];
#pragma unroll
            for (int mt = 0; mt < 2; mt++) {
                const int m = wm0 + mt * 16 + gid;
                af[mt][0] = f2tf(Ab[(m) * A_LD + k8 + tq]);
                af[mt][1] = f2tf(Ab[(m + 8) * A_LD + k8 + tq]);
                af[mt][2] = f2tf(Ab[(m) * A_LD + k8 + tq + 4]);
                af[mt][3] = f2tf(Ab[(m + 8) * A_LD + k8 + tq + 4]);
            }
#pragma unroll
            for (int nt = 0; nt < 8; nt++) {
                const int n = wn0 + nt * 8 + gid;
                bf[nt][0] = f2tf(Bb[(k8 + tq) * B_LD + n]);
                bf[nt][1] = f2tf(Bb[(k8 + tq + 4) * B_LD + n]);
            }
#pragma unroll
            for (int mt = 0; mt < 2; mt++)
#pragma unroll
                for (int nt = 0; nt < 8; nt++)
                    mma_tf32(acc[mt][nt], af[mt], bf[nt]);
        }
        __syncthreads();
    }

    // -------- epilogue --------
#pragma unroll
    for (int mt = 0; mt < 2; mt++) {
        const int r = row0 + wm0 + mt * 16 + gid;
#pragma unroll
        for (int nt = 0; nt < 8; nt++) {
            const int c = col0 + wn0 + nt * 8 + 2 * tq;
            float v0 = acc[mt][nt][0];
            float v1 = acc[mt][nt][1];
            float v2 = acc[mt][nt][2];
            float v3 = acc[mt][nt][3];
            if (EPI == 1) {
                v0 += bias[c]; v1 += bias[c + 1];
                v2 += bias[c]; v3 += bias[c + 1];
            } else if (EPI == 2) {
                v0 += bias[c]; v1 += bias[c + 1];
                v2 += bias[c]; v3 += bias[c + 1];
                v0 = 0.5f * v0 * (1.f + erff(v0 * 0.70710678118654752f));
                v1 = 0.5f * v1 * (1.f + erff(v1 * 0.70710678118654752f));
                v2 = 0.5f * v2 * (1.f + erff(v2 * 0.70710678118654752f));
                v3 = 0.5f * v3 * (1.f + erff(v3 * 0.70710678118654752f));
            } else if (EPI == 3) {
                float2 m0 = *(const float2*)&addm[(size_t)r * ldadd + c];
                float2 m1 = *(const float2*)&addm[(size_t)(r + 8) * ldadd + c];
                v0 += bias[c] + m0.x;     v1 += bias[c + 1] + m0.y;
                v2 += bias[c] + m1.x;     v3 += bias[c + 1] + m1.y;
            }
            if (TFOUT) {
                v0 = __uint_as_float(f2tf(v0));
                v1 = __uint_as_float(f2tf(v1));
                v2 = __uint_as_float(f2tf(v2));
                v3 = __uint_as_float(f2tf(v3));
            }
            *(float2*)&C[(size_t)r * ldc + c] = make_float2(v0, v1);
            *(float2*)&C[(size_t)(r + 8) * ldc + c] = make_float2(v2, v3);
        }
    }
}

// ---------------------------------------------------------------------------
// Flash attention v3: Q/K/V arrive pre-rounded to tf32 (no cvt at load).
// Q in smem (loaded once), K/V 2-stage cp.async, P fragments via shuffles.
// Grid (H, N/128). 8 warps, each owns 16 q-rows.
// smem: Qs[128][132] | Kst 2 x [64][132] | Vst 2 x [64][136]  (~200 KB)
// ---------------------------------------------------------------------------
#define QROWS 128
#define KTILE 64
#define Q_LDS 132
#define K_LDS 132
#define V_LDS 136
#define Q_SZ (QROWS * Q_LDS)
#define K_SZ (KTILE * K_LDS)
#define V_SZ (KTILE * V_LDS)

__global__ void __launch_bounds__(256, 1) flash_attn(
    const float* __restrict__ Q, const float* __restrict__ Km,
    const float* __restrict__ Vm, const float* __restrict__ adj,
    const float* __restrict__ adj_bias, float* __restrict__ AO, float scale)
{
    extern __shared__ float sm[];
    float* Qs  = sm;                       // 128 x 132  [row][dh]
    float* Kst = sm + Q_SZ;                // 2 x 64x132 [key][dh]
    float* Vst = Kst + 2 * K_SZ;           // 2 x 64x136 [key][dh]

    const int h  = blockIdx.x;
    const int q0 = blockIdx.y * QROWS;
    const int tid  = threadIdx.x;
    const int lane = tid & 31;
    const int wid  = tid >> 5;
    const int gid  = lane >> 2;
    const int tq   = lane & 3;
    const int wr0  = wid * 16;

    const float beta = adj_bias[h];

    // ---- Q tile: one cp.async group, consumed under the same wait as KV0 ----
    {
        const float* qb = Q + (size_t)q0 * DD_ + h * DH_;
#pragma unroll
        for (int i = 0; i < 16; i++) {
            int c = tid + i * 256;
            int row = c >> 5, off = (c & 31) * 4;
            CPA16(sm_u32(Qs + row * Q_LDS + off), qb + (size_t)row * DD_ + off);
        }
        CPCOMMIT();
    }

    auto issue = [&](int st, int j) {
        const float* kb = Km + (size_t)(j * KTILE) * DD_ + h * DH_;
        const float* vb = Vm + (size_t)(j * KTILE) * DD_ + h * DH_;
        float* kd = Kst + st * K_SZ;
        float* vd = Vst + st * V_SZ;
#pragma unroll
        for (int i = 0; i < 8; i++) {
            int c = tid + i * 256;
            int row = c >> 5, off = (c & 31) * 4;
            CPA16(sm_u32(kd + row * K_LDS + off), kb + (size_t)row * DD_ + off);
            CPA16(sm_u32(vd + row * V_LDS + off), vb + (size_t)row * DD_ + off);
        }
        CPCOMMIT();
    };

    float o[16][4];
#pragma unroll
    for (int nt = 0; nt < 16; nt++)
#pragma unroll
        for (int c = 0; c < 4; c++) o[nt][c] = 0.f;
    float m0 = -1e30f, m1 = -1e30f, l0 = 0.f, l1 = 0.f;

    const int NT = NN_ / KTILE;
    issue(0, 0);

    for (int j = 0; j < NT; j++) {
        if (j + 1 < NT) { issue((j + 1) & 1, j + 1); CPWAIT(1); }
        else            { CPWAIT(0); }
        __syncthreads();

        const float* Kb = Kst + (j & 1) * K_SZ;
        const float* Vb = Vst + (j & 1) * V_SZ;
        const float* Qw0 = Qs + (wr0 + gid) * Q_LDS;
        const float* Qw8 = Qw0 + 8 * Q_LDS;

        // ---- S = Q K^T  (all operands already tf32-rounded) ----
        float s[8][4];
#pragma unroll
        for (int nt = 0; nt < 8; nt++)
#pragma unroll
            for (int c = 0; c < 4; c++) s[nt][c] = 0.f;

#pragma unroll
        for (int ks = 0; ks < 16; ks++) {
            const int k8 = ks * 8;
            unsigned af[4];
            af[0] = __float_as_uint(Qw0[k8 + tq]);
            af[1] = __float_as_uint(Qw8[k8 + tq]);
            af[2] = __float_as_uint(Qw0[k8 + tq + 4]);
            af[3] = __float_as_uint(Qw8[k8 + tq + 4]);
#pragma unroll
            for (int nt = 0; nt < 8; nt++) {
                unsigned bf[2];
                bf[0] = __float_as_uint(Kb[(nt * 8 + gid) * K_LDS + k8 + tq]);
                bf[1] = __float_as_uint(Kb[(nt * 8 + gid) * K_LDS + k8 + tq + 4]);
                mma_tf32(s[nt], af, bf);
            }
        }

        // ---- scale + beta*adj ----
        const int kj0 = j * KTILE;
        const float* arow0 = adj + (size_t)(q0 + wr0 + gid) * NN_ + kj0;
        const float* arow1 = arow0 + (size_t)8 * NN_;
#pragma unroll
        for (int nt = 0; nt < 8; nt++) {
            const int c = nt * 8 + 2 * tq;
            float2 j0 = *(const float2*)(arow0 + c);
            float2 j1 = *(const float2*)(arow1 + c);
            s[nt][0] = s[nt][0] * scale + beta * j0.x;
            s[nt][1] = s[nt][1] * scale + beta * j0.y;
            s[nt][2] = s[nt][2] * scale + beta * j1.x;
            s[nt][3] = s[nt][3] * scale + beta * j1.y;
        }

        // ---- online softmax ----
        float mx0 = -1e30f, mx1 = -1e30f;
#pragma unroll
        for (int nt = 0; nt < 8; nt++) {
            mx0 = fmaxf(mx0, fmaxf(s[nt][0], s[nt][1]));
            mx1 = fmaxf(mx1, fmaxf(s[nt][2], s[nt][3]));
        }
        mx0 = fmaxf(mx0, __shfl_xor_sync(0xffffffffu, mx0, 1));
        mx0 = fmaxf(mx0, __shfl_xor_sync(0xffffffffu, mx0, 2));
        mx1 = fmaxf(mx1, __shfl_xor_sync(0xffffffffu, mx1, 1));
        mx1 = fmaxf(mx1, __shfl_xor_sync(0xffffffffu, mx1, 2));

        const float mn0 = fmaxf(m0, mx0);
        const float mn1 = fmaxf(m1, mx1);
        const float f0 = __expf(m0 - mn0);
        const float f1 = __expf(m1 - mn1);
        m0 = mn0; m1 = mn1;

        float sum0 = 0.f, sum1 = 0.f;
#pragma unroll
        for (int nt = 0; nt < 8; nt++) {
            s[nt][0] = __expf(s[nt][0] - mn0);
            s[nt][1] = __expf(s[nt][1] - mn0);
            s[nt][2] = __expf(s[nt][2] - mn1);
            s[nt][3] = __expf(s[nt][3] - mn1);
            sum0 += s[nt][0] + s[nt][1];
            sum1 += s[nt][2] + s[nt][3];
        }
        sum0 += __shfl_xor_sync(0xffffffffu, sum0, 1);
        sum0 += __shfl_xor_sync(0xffffffffu, sum0, 2);
        sum1 += __shfl_xor_sync(0xffffffffu, sum1, 1);
        sum1 += __shfl_xor_sync(0xffffffffu, sum1, 2);
        l0 = l0 * f0 + sum0;
        l1 = l1 * f1 + sum1;

#pragma unroll
        for (int nt = 0; nt < 16; nt++) {
            o[nt][0] *= f0; o[nt][1] *= f0;
            o[nt][2] *= f1; o[nt][3] *= f1;
        }

        // ---- O += P @ V : P A-fragments via shuffles ----
        const int src0 = (lane & 28) | (tq >> 1);
        const int src1 = src0 + 2;
        const bool odd = (tq & 1);
#pragma unroll
        for (int kt = 0; kt < 8; kt++) {
            float e0 = __shfl_sync(0xffffffffu, s[kt][0], src0);
            float e1 = __shfl_sync(0xffffffffu, s[kt][1], src0);
            float e2 = __shfl_sync(0xffffffffu, s[kt][2], src0);
            float e3 = __shfl_sync(0xffffffffu, s[kt][3], src0);
            float g0 = __shfl_sync(0xffffffffu, s[kt][0], src1);
            float g1 = __shfl_sync(0xffffffffu, s[kt][1], src1);
            float g2 = __shfl_sync(0xffffffffu, s[kt][2], src1);
            float g3 = __shfl_sync(0xffffffffu, s[kt][3], src1);
            unsigned af[4];
            af[0] = f2tf(odd ? e1 : e0);
            af[1] = f2tf(odd ? e3 : e2);
            af[2] = f2tf(odd ? g1 : g0);
            af[3] = f2tf(odd ? g3 : g2);
            const int k8 = kt * 8;
#pragma unroll
            for (int nt = 0; nt < 16; nt++) {
                unsigned bf[2];
                bf[0] = __float_as_uint(Vb[(k8 + tq) * V_LDS + nt * 8 + gid]);
                bf[1] = __float_as_uint(Vb[(k8 + tq + 4) * V_LDS + nt * 8 + gid]);
                mma_tf32(o[nt], af, bf);
            }
        }
        __syncthreads();
    }

    // ---- normalize and write out ----
    const float inv0 = 1.0f / l0;
    const float inv1 = 1.0f / l1;
    float* o0 = AO + (size_t)(q0 + wr0 + gid) * DD_ + h * DH_;
    float* o1 = o0 + (size_t)8 * DD_;
#pragma unroll
    for (int nt = 0; nt < 16; nt++) {
        const int c = nt * 8 + 2 * tq;
        *(float2*)(o0 + c) = make_float2(o[nt][0] * inv0, o[nt][1] * inv0);
        *(float2*)(o1 + c) = make_float2(o[nt][2] * inv1, o[nt][3] * inv1);
    }
}

// ---------------------------------------------------------------------------
// Row LayerNorm over D=1024: out = LN(X + R) * g + b   (R optional)
// ---------------------------------------------------------------------------
__global__ void __launch_bounds__(256) ln_row(
    const float* __restrict__ X, const float* __restrict__ R,
    const float* __restrict__ g, const float* __restrict__ b,
    float* __restrict__ out)
{
    __shared__ float red[256];
    const int tid = threadIdx.x;
    const size_t row = blockIdx.x;

    float4 v = ((const float4*)(X + row * DD_))[tid];
    if (R) {
        float4 r = ((const float4*)(R + row * DD_))[tid];
        v.x += r.x; v.y += r.y; v.z += r.z; v.w += r.w;
    }
    red[tid] = v.x + v.y + v.z + v.w;
    __syncthreads();
    for (int s = 128; s > 0; s >>= 1) {
        if (tid < s) red[tid] += red[tid + s];
        __syncthreads();
    }
    const float mu = red[0] * (1.0f / DD_);
    __syncthreads();

    float dx = v.x - mu, dy = v.y - mu, dz = v.z - mu, dw = v.w - mu;
    red[tid] = dx * dx + dy * dy + dz * dz + dw * dw;
    __syncthreads();
    for (int s = 128; s > 0; s >>= 1) {
        if (tid < s) red[tid] += red[tid + s];
        __syncthreads();
    }
    const float rs = rsqrtf(red[0] * (1.0f / DD_) + 1e-5f);

    float4 gg = ((const float4*)g)[tid];
    float4 bb = ((const float4*)b)[tid];
    float4 o;
    o.x = dx * rs * gg.x + bb.x;
    o.y = dy * rs * gg.y + bb.y;
    o.z = dz * rs * gg.z + bb.z;
    o.w = dw * rs * gg.w + bb.w;
    ((float4*)(out + row * DD_))[tid] = o;
}

// ---------------------------------------------------------------------------
extern "C" void kernel_launch(void* const* d_in, const int* in_sizes, int n_in,
                              void* d_out, int out_size)
{
    const float* x        = (const float*)d_in[0];
    const float* adj      = (const float*)d_in[1];
    const float* Wq       = (const float*)d_in[2];
    const float* Wk       = (const float*)d_in[3];
    const float* Wv       = (const float*)d_in[4];
    const float* Wo_w     = (const float*)d_in[5];
    const float* Wo_b     = (const float*)d_in[6];
    const float* adj_bias = (const float*)d_in[7];
    const float* ln1_g    = (const float*)d_in[8];
    const float* ln1_b    = (const float*)d_in[9];
    const float* ffn_ln_g = (const float*)d_in[10];
    const float* ffn_ln_b = (const float*)d_in[11];
    const float* ffn_w1   = (const float*)d_in[12];
    const float* ffn_b1   = (const float*)d_in[13];
    const float* ffn_w2   = (const float*)d_in[14];
    const float* ffn_b2   = (const float*)d_in[15];
    float* out = (float*)d_out;

    float* scr = nullptr;
    cudaGetSymbolAddress((void**)&scr, g_scratch);

    float* Q  = scr + 0 * SZ_ND;
    float* Kb = scr + 1 * SZ_ND;
    float* V  = scr + 2 * SZ_ND;
    float* AO = scr + 3 * SZ_ND;
    float* P  = scr + 4 * SZ_ND;
    float* Hb = scr + 5 * SZ_ND;
    float* Fb = scr + 6 * SZ_ND;
    float* T  = scr + 7 * SZ_ND;

    const int TH = 256;
    const float scale = 0.08838834764831845f;  // 128^-0.5

    const int GEMM_SMEM  = (2 * A_SZ + 2 * B_SZ) * 4;                  // 71,680 B
    const int FLASH_SMEM = (Q_SZ + 2 * K_SZ + 2 * V_SZ) * 4;           // 204,800 B
    static int attr_set = 0;
    if (!attr_set) {
        cudaFuncSetAttribute(gemm_tc<0, true>,  cudaFuncAttributeMaxDynamicSharedMemorySize, GEMM_SMEM);
        cudaFuncSetAttribute(gemm_tc<1, false>, cudaFuncAttributeMaxDynamicSharedMemorySize, GEMM_SMEM);
        cudaFuncSetAttribute(gemm_tc<2, false>, cudaFuncAttributeMaxDynamicSharedMemorySize, GEMM_SMEM);
        cudaFuncSetAttribute(gemm_tc<3, false>, cudaFuncAttributeMaxDynamicSharedMemorySize, GEMM_SMEM);
        cudaFuncSetAttribute(flash_attn, cudaFuncAttributeMaxDynamicSharedMemorySize, FLASH_SMEM);
        attr_set = 1;
    }

    // --- Q/K/V projections (outputs pre-rounded to tf32 for flash)
    dim3 gqkv(DD_ / BN, NN_ / BM);
    gemm_tc<0, true><<<gqkv, TH, GEMM_SMEM>>>(x, Wq, Q, DD_, DD_, DD_, DD_, nullptr, nullptr, 0);
    gemm_tc<0, true><<<gqkv, TH, GEMM_SMEM>>>(x, Wk, Kb, DD_, DD_, DD_, DD_, nullptr, nullptr, 0);
    gemm_tc<0, true><<<gqkv, TH, GEMM_SMEM>>>(x, Wv, V, DD_, DD_, DD_, DD_, nullptr, nullptr, 0);

    // --- Fused attention (scores + adj bias + softmax + @V)
    flash_attn<<<dim3(HH_, NN_ / QROWS), TH, FLASH_SMEM>>>(Q, Kb, V, adj, adj_bias, AO, scale);

    // --- Output projection with bias
    gemm_tc<1, false><<<gqkv, TH, GEMM_SMEM>>>(AO, Wo_w, P, DD_, DD_, DD_, DD_, Wo_b, nullptr, 0);

    // --- h = LN(x + P);  f = LN(h)
    ln_row<<<NN_, TH>>>(x, P, ln1_g, ln1_b, Hb);
    ln_row<<<NN_, TH>>>(Hb, nullptr, ffn_ln_g, ffn_ln_b, Fb);

    // --- FFN1 with fused exact GELU
    dim3 gf1(FF_ / BN, NN_ / BM);
    gemm_tc<2, false><<<gf1, TH, GEMM_SMEM>>>(Fb, ffn_w1, T, DD_, DD_, FF_, FF_, ffn_b1, nullptr, 0);

    // --- FFN2 + bias + residual h
    dim3 gf2(DD_ / BN, NN_ / BM);
    gemm_tc<3, false><<<gf2, TH, GEMM_SMEM>>>(T, ffn_w2, out, FF_, FF_, DD_, DD_, ffn_b2, Hb, DD_);
}

// round 13
// speedup vs baseline: 3.3029x; 1.0134x over previous
#include <cuda_runtime.h>
#include <math.h>

// Problem constants
#define NN_ 4096
#define DD_ 1024
#define HH_ 8
#define DH_ 128
#define FF_ 2048   // 2*D

static const size_t SZ_ND = (size_t)NN_ * DD_;      // 4,194,304
static const size_t SZ_NF = (size_t)NN_ * FF_;      // 8,388,608

// Scratch: Q,K,V,AO,P,H,F (7*SZ_ND) | T (SZ_NF) | x_tf (SZ_ND)
//          | Wq,Wk,Wv,Wo_tf (4 x 1M) | W1_tf,W2_tf (2 x 2M)
__device__ float g_scratch[12 * 4194304ull];

// ---------------------------------------------------------------------------
// TF32 + cp.async helpers
// ---------------------------------------------------------------------------
__device__ __forceinline__ unsigned f2tf(float f) {
    unsigned u;
    asm("cvt.rna.tf32.f32 %0, %1;" : "=r"(u) : "f"(f));
    return u;
}

__device__ __forceinline__ void mma_tf32(float* d, const unsigned* a, const unsigned* b) {
    asm volatile(
        "mma.sync.aligned.m16n8k8.row.col.f32.tf32.tf32.f32 "
        "{%0,%1,%2,%3}, {%4,%5,%6,%7}, {%8,%9}, {%0,%1,%2,%3};"
        : "+f"(d[0]), "+f"(d[1]), "+f"(d[2]), "+f"(d[3])
        : "r"(a[0]), "r"(a[1]), "r"(a[2]), "r"(a[3]), "r"(b[0]), "r"(b[1]));
}

__device__ __forceinline__ unsigned sm_u32(const void* p) {
    return (unsigned)__cvta_generic_to_shared(p);
}
#define CPA16(s, g) asm volatile("cp.async.cg.shared.global [%0], [%1], 16;" :: "r"(s), "l"(g))
#define CPCOMMIT()  asm volatile("cp.async.commit_group;")
#define CPWAIT(n)   asm volatile("cp.async.wait_group %0;" :: "n"(n))

// ---------------------------------------------------------------------------
// Round a tensor to tf32 bit pattern (element-wise), float4 vectorized.
// ---------------------------------------------------------------------------
__global__ void __launch_bounds__(256) round_tf_k(
    const float* __restrict__ in, float* __restrict__ out, int n4)
{
    int i = blockIdx.x * 256 + threadIdx.x;
    if (i < n4) {
        float4 v = ((const float4*)in)[i];
        v.x = __uint_as_float(f2tf(v.x));
        v.y = __uint_as_float(f2tf(v.y));
        v.z = __uint_as_float(f2tf(v.z));
        v.w = __uint_as_float(f2tf(v.w));
        ((float4*)out)[i] = v;
    }
}

// ---------------------------------------------------------------------------
// TF32 tensor-core GEMM: C = A @ B.  128x128 tile, BK=32, 2-stage cp.async.
// ALL operands pre-rounded to tf32 — no cvt in the mainloop.
// EPI: 0 = none, 1 = +bias[col], 2 = gelu(+bias), 3 = +bias + addm
// TFOUT: store outputs pre-rounded to tf32 (consumer skips cvt).
// ---------------------------------------------------------------------------
#define BM 128
#define BN 128
#define GBK 32
#define A_LD 36
#define B_LD 136
#define A_SZ (BM * A_LD)
#define B_SZ (GBK * B_LD)

template <int EPI, bool TFOUT>
__global__ void __launch_bounds__(256, 2) gemm_tc(
    const float* __restrict__ A, const float* __restrict__ B, float* __restrict__ C,
    int K, int lda, int ldb, int ldc,
    const float* __restrict__ bias,
    const float* __restrict__ addm, int ldadd)
{
    extern __shared__ float smg[];
    float* As = smg;               // 2 stages x 128x36
    float* Bs = smg + 2 * A_SZ;    // 2 stages x 32x136

    const int tid  = threadIdx.x;
    const int lane = tid & 31;
    const int wid  = tid >> 5;
    const int gid  = lane >> 2;
    const int tq   = lane & 3;
    const int wm0  = (wid & 3) * 32;
    const int wn0  = (wid >> 2) * 64;
    const int row0 = blockIdx.y * BM;
    const int col0 = blockIdx.x * BN;

    auto issue = [&](int st, int k0) {
        float* ad = As + st * A_SZ;
        float* bd = Bs + st * B_SZ;
#pragma unroll
        for (int i = 0; i < 4; i++) {
            int c = tid + i * 256;
            int row = c >> 3, ko = (c & 7) * 4;
            CPA16(sm_u32(ad + row * A_LD + ko), A + (size_t)(row0 + row) * lda + k0 + ko);
        }
#pragma unroll
        for (int i = 0; i < 4; i++) {
            int c = tid + i * 256;
            int row = c >> 5, no = (c & 31) * 4;
            CPA16(sm_u32(bd + row * B_LD + no), B + (size_t)(k0 + row) * ldb + col0 + no);
        }
        CPCOMMIT();
    };

    float acc[2][8][4];
#pragma unroll
    for (int mt = 0; mt < 2; mt++)
#pragma unroll
        for (int nt = 0; nt < 8; nt++)
#pragma unroll
            for (int c = 0; c < 4; c++) acc[mt][nt][c] = 0.f;

    const int KT = K / GBK;
    issue(0, 0);

    for (int it = 0; it < KT; it++) {
        if (it + 1 < KT) { issue((it + 1) & 1, (it + 1) * GBK); CPWAIT(1); }
        else             { CPWAIT(0); }
        __syncthreads();

        const float* Ab = As + (it & 1) * A_SZ;
        const float* Bb = Bs + (it & 1) * B_SZ;
#pragma unroll
        for (int ks = 0; ks < 4; ks++) {
            const int k8 = ks * 8;
            unsigned af[2][4], bf[8][2];
#pragma unroll
            for (int mt = 0; mt < 2; mt++) {
                const int m = wm0 + mt * 16 + gid;
                af[mt][0] = __float_as_uint(Ab[(m) * A_LD + k8 + tq]);
                af[mt][1] = __float_as_uint(Ab[(m + 8) * A_LD + k8 + tq]);
                af[mt][2] = __float_as_uint(Ab[(m) * A_LD + k8 + tq + 4]);
                af[mt][3] = __float_as_uint(Ab[(m + 8) * A_LD + k8 + tq + 4]);
            }
#pragma unroll
            for (int nt = 0; nt < 8; nt++) {
                const int n = wn0 + nt * 8 + gid;
                bf[nt][0] = __float_as_uint(Bb[(k8 + tq) * B_LD + n]);
                bf[nt][1] = __float_as_uint(Bb[(k8 + tq + 4) * B_LD + n]);
            }
#pragma unroll
            for (int mt = 0; mt < 2; mt++)
#pragma unroll
                for (int nt = 0; nt < 8; nt++)
                    mma_tf32(acc[mt][nt], af[mt], bf[nt]);
        }
        __syncthreads();
    }

    // -------- epilogue --------
#pragma unroll
    for (int mt = 0; mt < 2; mt++) {
        const int r = row0 + wm0 + mt * 16 + gid;
#pragma unroll
        for (int nt = 0; nt < 8; nt++) {
            const int c = col0 + wn0 + nt * 8 + 2 * tq;
            float v0 = acc[mt][nt][0];
            float v1 = acc[mt][nt][1];
            float v2 = acc[mt][nt][2];
            float v3 = acc[mt][nt][3];
            if (EPI == 1) {
                v0 += bias[c]; v1 += bias[c + 1];
                v2 += bias[c]; v3 += bias[c + 1];
            } else if (EPI == 2) {
                v0 += bias[c]; v1 += bias[c + 1];
                v2 += bias[c]; v3 += bias[c + 1];
                v0 = 0.5f * v0 * (1.f + erff(v0 * 0.70710678118654752f));
                v1 = 0.5f * v1 * (1.f + erff(v1 * 0.70710678118654752f));
                v2 = 0.5f * v2 * (1.f + erff(v2 * 0.70710678118654752f));
                v3 = 0.5f * v3 * (1.f + erff(v3 * 0.70710678118654752f));
            } else if (EPI == 3) {
                float2 m0 = *(const float2*)&addm[(size_t)r * ldadd + c];
                float2 m1 = *(const float2*)&addm[(size_t)(r + 8) * ldadd + c];
                v0 += bias[c] + m0.x;     v1 += bias[c + 1] + m0.y;
                v2 += bias[c] + m1.x;     v3 += bias[c + 1] + m1.y;
            }
            if (TFOUT) {
                v0 = __uint_as_float(f2tf(v0));
                v1 = __uint_as_float(f2tf(v1));
                v2 = __uint_as_float(f2tf(v2));
                v3 = __uint_as_float(f2tf(v3));
            }
            *(float2*)&C[(size_t)r * ldc + c] = make_float2(v0, v1);
            *(float2*)&C[(size_t)(r + 8) * ldc + c] = make_float2(v2, v3);
        }
    }
}

// ---------------------------------------------------------------------------
// Flash attention v4: Q/K/V pre-rounded tf32; adj loads hoisted above QK MMAs.
// Q in smem (loaded once), K/V 2-stage cp.async, P fragments via shuffles.
// Grid (H, N/128). 8 warps, each owns 16 q-rows. AO written tf32-rounded.
// ---------------------------------------------------------------------------
#define QROWS 128
#define KTILE 64
#define Q_LDS 132
#define K_LDS 132
#define V_LDS 136
#define Q_SZ (QROWS * Q_LDS)
#define K_SZ (KTILE * K_LDS)
#define V_SZ (KTILE * V_LDS)

__global__ void __launch_bounds__(256, 1) flash_attn(
    const float* __restrict__ Q, const float* __restrict__ Km,
    const float* __restrict__ Vm, const float* __restrict__ adj,
    const float* __restrict__ adj_bias, float* __restrict__ AO, float scale)
{
    extern __shared__ float sm[];
    float* Qs  = sm;                       // 128 x 132  [row][dh]
    float* Kst = sm + Q_SZ;                // 2 x 64x132 [key][dh]
    float* Vst = Kst + 2 * K_SZ;           // 2 x 64x136 [key][dh]

    const int h  = blockIdx.x;
    const int q0 = blockIdx.y * QROWS;
    const int tid  = threadIdx.x;
    const int lane = tid & 31;
    const int wid  = tid >> 5;
    const int gid  = lane >> 2;
    const int tq   = lane & 3;
    const int wr0  = wid * 16;

    const float beta = adj_bias[h];

    // ---- Q tile: one cp.async group, consumed under the same wait as KV0 ----
    {
        const float* qb = Q + (size_t)q0 * DD_ + h * DH_;
#pragma unroll
        for (int i = 0; i < 16; i++) {
            int c = tid + i * 256;
            int row = c >> 5, off = (c & 31) * 4;
            CPA16(sm_u32(Qs + row * Q_LDS + off), qb + (size_t)row * DD_ + off);
        }
        CPCOMMIT();
    }

    auto issue = [&](int st, int j) {
        const float* kb = Km + (size_t)(j * KTILE) * DD_ + h * DH_;
        const float* vb = Vm + (size_t)(j * KTILE) * DD_ + h * DH_;
        float* kd = Kst + st * K_SZ;
        float* vd = Vst + st * V_SZ;
#pragma unroll
        for (int i = 0; i < 8; i++) {
            int c = tid + i * 256;
            int row = c >> 5, off = (c & 31) * 4;
            CPA16(sm_u32(kd + row * K_LDS + off), kb + (size_t)row * DD_ + off);
            CPA16(sm_u32(vd + row * V_LDS + off), vb + (size_t)row * DD_ + off);
        }
        CPCOMMIT();
    };

    float o[16][4];
#pragma unroll
    for (int nt = 0; nt < 16; nt++)
#pragma unroll
        for (int c = 0; c < 4; c++) o[nt][c] = 0.f;
    float m0 = -1e30f, m1 = -1e30f, l0 = 0.f, l1 = 0.f;

    const int NT = NN_ / KTILE;
    issue(0, 0);

    const float* arow_base0 = adj + (size_t)(q0 + wr0 + gid) * NN_;
    const float* arow_base1 = arow_base0 + (size_t)8 * NN_;

    for (int j = 0; j < NT; j++) {
        if (j + 1 < NT) { issue((j + 1) & 1, j + 1); CPWAIT(1); }
        else            { CPWAIT(0); }
        __syncthreads();

        // ---- hoisted adj loads: in flight during the QK MMA block ----
        const int kj0 = j * KTILE;
        float2 aj0[8], aj1[8];
#pragma unroll
        for (int nt = 0; nt < 8; nt++) {
            const int c = kj0 + nt * 8 + 2 * tq;
            aj0[nt] = *(const float2*)(arow_base0 + c);
            aj1[nt] = *(const float2*)(arow_base1 + c);
        }

        const float* Kb = Kst + (j & 1) * K_SZ;
        const float* Vb = Vst + (j & 1) * V_SZ;
        const float* Qw0 = Qs + (wr0 + gid) * Q_LDS;
        const float* Qw8 = Qw0 + 8 * Q_LDS;

        // ---- S = Q K^T ----
        float s[8][4];
#pragma unroll
        for (int nt = 0; nt < 8; nt++)
#pragma unroll
            for (int c = 0; c < 4; c++) s[nt][c] = 0.f;

#pragma unroll
        for (int ks = 0; ks < 16; ks++) {
            const int k8 = ks * 8;
            unsigned af[4];
            af[0] = __float_as_uint(Qw0[k8 + tq]);
            af[1] = __float_as_uint(Qw8[k8 + tq]);
            af[2] = __float_as_uint(Qw0[k8 + tq + 4]);
            af[3] = __float_as_uint(Qw8[k8 + tq + 4]);
#pragma unroll
            for (int nt = 0; nt < 8; nt++) {
                unsigned bf[2];
                bf[0] = __float_as_uint(Kb[(nt * 8 + gid) * K_LDS + k8 + tq]);
                bf[1] = __float_as_uint(Kb[(nt * 8 + gid) * K_LDS + k8 + tq + 4]);
                mma_tf32(s[nt], af, bf);
            }
        }

        // ---- scale + beta*adj (adj already in registers) ----
#pragma unroll
        for (int nt = 0; nt < 8; nt++) {
            s[nt][0] = s[nt][0] * scale + beta * aj0[nt].x;
            s[nt][1] = s[nt][1] * scale + beta * aj0[nt].y;
            s[nt][2] = s[nt][2] * scale + beta * aj1[nt].x;
            s[nt][3] = s[nt][3] * scale + beta * aj1[nt].y;
        }

        // ---- online softmax ----
        float mx0 = -1e30f, mx1 = -1e30f;
#pragma unroll
        for (int nt = 0; nt < 8; nt++) {
            mx0 = fmaxf(mx0, fmaxf(s[nt][0], s[nt][1]));
            mx1 = fmaxf(mx1, fmaxf(s[nt][2], s[nt][3]));
        }
        mx0 = fmaxf(mx0, __shfl_xor_sync(0xffffffffu, mx0, 1));
        mx0 = fmaxf(mx0, __shfl_xor_sync(0xffffffffu, mx0, 2));
        mx1 = fmaxf(mx1, __shfl_xor_sync(0xffffffffu, mx1, 1));
        mx1 = fmaxf(mx1, __shfl_xor_sync(0xffffffffu, mx1, 2));

        const float mn0 = fmaxf(m0, mx0);
        const float mn1 = fmaxf(m1, mx1);
        const float f0 = __expf(m0 - mn0);
        const float f1 = __expf(m1 - mn1);
        m0 = mn0; m1 = mn1;

        float sum0 = 0.f, sum1 = 0.f;
#pragma unroll
        for (int nt = 0; nt < 8; nt++) {
            s[nt][0] = __expf(s[nt][0] - mn0);
            s[nt][1] = __expf(s[nt][1] - mn0);
            s[nt][2] = __expf(s[nt][2] - mn1);
            s[nt][3] = __expf(s[nt][3] - mn1);
            sum0 += s[nt][0] + s[nt][1];
            sum1 += s[nt][2] + s[nt][3];
        }
        sum0 += __shfl_xor_sync(0xffffffffu, sum0, 1);
        sum0 += __shfl_xor_sync(0xffffffffu, sum0, 2);
        sum1 += __shfl_xor_sync(0xffffffffu, sum1, 1);
        sum1 += __shfl_xor_sync(0xffffffffu, sum1, 2);
        l0 = l0 * f0 + sum0;
        l1 = l1 * f1 + sum1;

#pragma unroll
        for (int nt = 0; nt < 16; nt++) {
            o[nt][0] *= f0; o[nt][1] *= f0;
            o[nt][2] *= f1; o[nt][3] *= f1;
        }

        // ---- O += P @ V : P A-fragments via shuffles ----
        const int src0 = (lane & 28) | (tq >> 1);
        const int src1 = src0 + 2;
        const bool odd = (tq & 1);
#pragma unroll
        for (int kt = 0; kt < 8; kt++) {
            float e0 = __shfl_sync(0xffffffffu, s[kt][0], src0);
            float e1 = __shfl_sync(0xffffffffu, s[kt][1], src0);
            float e2 = __shfl_sync(0xffffffffu, s[kt][2], src0);
            float e3 = __shfl_sync(0xffffffffu, s[kt][3], src0);
            float g0 = __shfl_sync(0xffffffffu, s[kt][0], src1);
            float g1 = __shfl_sync(0xffffffffu, s[kt][1], src1);
            float g2 = __shfl_sync(0xffffffffu, s[kt][2], src1);
            float g3 = __shfl_sync(0xffffffffu, s[kt][3], src1);
            unsigned af[4];
            af[0] = f2tf(odd ? e1 : e0);
            af[1] = f2tf(odd ? e3 : e2);
            af[2] = f2tf(odd ? g1 : g0);
            af[3] = f2tf(odd ? g3 : g2);
            const int k8 = kt * 8;
#pragma unroll
            for (int nt = 0; nt < 16; nt++) {
                unsigned bf[2];
                bf[0] = __float_as_uint(Vb[(k8 + tq) * V_LDS + nt * 8 + gid]);
                bf[1] = __float_as_uint(Vb[(k8 + tq + 4) * V_LDS + nt * 8 + gid]);
                mma_tf32(o[nt], af, bf);
            }
        }
        __syncthreads();
    }

    // ---- normalize, round to tf32 (consumer is a GEMM A-operand), write ----
    const float inv0 = 1.0f / l0;
    const float inv1 = 1.0f / l1;
    float* o0 = AO + (size_t)(q0 + wr0 + gid) * DD_ + h * DH_;
    float* o1 = o0 + (size_t)8 * DD_;
#pragma unroll
    for (int nt = 0; nt < 16; nt++) {
        const int c = nt * 8 + 2 * tq;
        float a0 = __uint_as_float(f2tf(o[nt][0] * inv0));
        float a1 = __uint_as_float(f2tf(o[nt][1] * inv0));
        float a2 = __uint_as_float(f2tf(o[nt][2] * inv1));
        float a3 = __uint_as_float(f2tf(o[nt][3] * inv1));
        *(float2*)(o0 + c) = make_float2(a0, a1);
        *(float2*)(o1 + c) = make_float2(a2, a3);
    }
}

// ---------------------------------------------------------------------------
// Row LayerNorm over D=1024: out = LN(X + R) * g + b   (R optional)
// TFOUT rounds output to tf32 (for GEMM consumers).
// ---------------------------------------------------------------------------
template <bool TFOUT>
__global__ void __launch_bounds__(256) ln_row(
    const float* __restrict__ X, const float* __restrict__ R,
    const float* __restrict__ g, const float* __restrict__ b,
    float* __restrict__ out)
{
    __shared__ float red[256];
    const int tid = threadIdx.x;
    const size_t row = blockIdx.x;

    float4 v = ((const float4*)(X + row * DD_))[tid];
    if (R) {
        float4 r = ((const float4*)(R + row * DD_))[tid];
        v.x += r.x; v.y += r.y; v.z += r.z; v.w += r.w;
    }
    red[tid] = v.x + v.y + v.z + v.w;
    __syncthreads();
    for (int s = 128; s > 0; s >>= 1) {
        if (tid < s) red[tid] += red[tid + s];
        __syncthreads();
    }
    const float mu = red[0] * (1.0f / DD_);
    __syncthreads();

    float dx = v.x - mu, dy = v.y - mu, dz = v.z - mu, dw = v.w - mu;
    red[tid] = dx * dx + dy * dy + dz * dz + dw * dw;
    __syncthreads();
    for (int s = 128; s > 0; s >>= 1) {
        if (tid < s) red[tid] += red[tid + s];
        __syncthreads();
    }
    const float rs = rsqrtf(red[0] * (1.0f / DD_) + 1e-5f);

    float4 gg = ((const float4*)g)[tid];
    float4 bb = ((const float4*)b)[tid];
    float4 o;
    o.x = dx * rs * gg.x + bb.x;
    o.y = dy * rs * gg.y + bb.y;
    o.z = dz * rs * gg.z + bb.z;
    o.w = dw * rs * gg.w + bb.w;
    if (TFOUT) {
        o.x = __uint_as_float(f2tf(o.x));
        o.y = __uint_as_float(f2tf(o.y));
        o.z = __uint_as_float(f2tf(o.z));
        o.w = __uint_as_float(f2tf(o.w));
    }
    ((float4*)(out + row * DD_))[tid] = o;
}

// ---------------------------------------------------------------------------
extern "C" void kernel_launch(void* const* d_in, const int* in_sizes, int n_in,
                              void* d_out, int out_size)
{
    const float* x        = (const float*)d_in[0];
    const float* adj      = (const float*)d_in[1];
    const float* Wq       = (const float*)d_in[2];
    const float* Wk       = (const float*)d_in[3];
    const float* Wv       = (const float*)d_in[4];
    const float* Wo_w     = (const float*)d_in[5];
    const float* Wo_b     = (const float*)d_in[6];
    const float* adj_bias = (const float*)d_in[7];
    const float* ln1_g    = (const float*)d_in[8];
    const float* ln1_b    = (const float*)d_in[9];
    const float* ffn_ln_g = (const float*)d_in[10];
    const float* ffn_ln_b = (const float*)d_in[11];
    const float* ffn_w1   = (const float*)d_in[12];
    const float* ffn_b1   = (const float*)d_in[13];
    const float* ffn_w2   = (const float*)d_in[14];
    const float* ffn_b2   = (const float*)d_in[15];
    float* out = (float*)d_out;

    float* scr = nullptr;
    cudaGetSymbolAddress((void**)&scr, g_scratch);

    float* Q    = scr + 0 * SZ_ND;
    float* Kb   = scr + 1 * SZ_ND;
    float* V    = scr + 2 * SZ_ND;
    float* AO   = scr + 3 * SZ_ND;
    float* P    = scr + 4 * SZ_ND;
    float* Hb   = scr + 5 * SZ_ND;
    float* Fb   = scr + 6 * SZ_ND;
    float* T    = scr + 7 * SZ_ND;              // SZ_NF = 2*SZ_ND
    float* x_tf = scr + 9 * SZ_ND;
    float* Wq_tf = scr + 10 * SZ_ND;            // 4 x 1M weights
    float* Wk_tf = Wq_tf + (size_t)DD_ * DD_;
    float* Wv_tf = Wk_tf + (size_t)DD_ * DD_;
    float* Wo_tf = Wv_tf + (size_t)DD_ * DD_;
    float* W1_tf = scr + 11 * SZ_ND;            // 2M
    float* W2_tf = W1_tf + (size_t)DD_ * FF_;   // needs 2M -> total 12*SZ_ND? fits: 11*SZ_ND + 4M = 12*SZ_ND

    const int TH = 256;
    const float scale = 0.08838834764831845f;  // 128^-0.5

    const int GEMM_SMEM  = (2 * A_SZ + 2 * B_SZ) * 4;                  // 71,680 B
    const int FLASH_SMEM = (Q_SZ + 2 * K_SZ + 2 * V_SZ) * 4;           // 204,800 B
    static int attr_set = 0;
    if (!attr_set) {
        cudaFuncSetAttribute(gemm_tc<0, true>,  cudaFuncAttributeMaxDynamicSharedMemorySize, GEMM_SMEM);
        cudaFuncSetAttribute(gemm_tc<1, false>, cudaFuncAttributeMaxDynamicSharedMemorySize, GEMM_SMEM);
        cudaFuncSetAttribute(gemm_tc<2, true>,  cudaFuncAttributeMaxDynamicSharedMemorySize, GEMM_SMEM);
        cudaFuncSetAttribute(gemm_tc<3, false>, cudaFuncAttributeMaxDynamicSharedMemorySize, GEMM_SMEM);
        cudaFuncSetAttribute(flash_attn, cudaFuncAttributeMaxDynamicSharedMemorySize, FLASH_SMEM);
        attr_set = 1;
    }

    // --- Pre-round x + all weights to tf32 (bit-identical to cvt-at-load)
    round_tf_k<<<(int)(SZ_ND / 4 + 255) / 256, TH>>>(x, x_tf, (int)(SZ_ND / 4));
    round_tf_k<<<(DD_ * DD_ / 4 + 255) / 256, TH>>>(Wq, Wq_tf, DD_ * DD_ / 4);
    round_tf_k<<<(DD_ * DD_ / 4 + 255) / 256, TH>>>(Wk, Wk_tf, DD_ * DD_ / 4);
    round_tf_k<<<(DD_ * DD_ / 4 + 255) / 256, TH>>>(Wv, Wv_tf, DD_ * DD_ / 4);
    round_tf_k<<<(DD_ * DD_ / 4 + 255) / 256, TH>>>(Wo_w, Wo_tf, DD_ * DD_ / 4);
    round_tf_k<<<(DD_ * FF_ / 4 + 255) / 256, TH>>>(ffn_w1, W1_tf, DD_ * FF_ / 4);
    round_tf_k<<<(FF_ * DD_ / 4 + 255) / 256, TH>>>(ffn_w2, W2_tf, FF_ * DD_ / 4);

    // --- Q/K/V projections (outputs pre-rounded to tf32 for flash)
    dim3 gqkv(DD_ / BN, NN_ / BM);
    gemm_tc<0, true><<<gqkv, TH, GEMM_SMEM>>>(x_tf, Wq_tf, Q, DD_, DD_, DD_, DD_, nullptr, nullptr, 0);
    gemm_tc<0, true><<<gqkv, TH, GEMM_SMEM>>>(x_tf, Wk_tf, Kb, DD_, DD_, DD_, DD_, nullptr, nullptr, 0);
    gemm_tc<0, true><<<gqkv, TH, GEMM_SMEM>>>(x_tf, Wv_tf, V, DD_, DD_, DD_, DD_, nullptr, nullptr, 0);

    // --- Fused attention (scores + adj bias + softmax + @V); AO tf32-rounded
    flash_attn<<<dim3(HH_, NN_ / QROWS), TH, FLASH_SMEM>>>(Q, Kb, V, adj, adj_bias, AO, scale);

    // --- Output projection with bias (fp32 out)
    gemm_tc<1, false><<<gqkv, TH, GEMM_SMEM>>>(AO, Wo_tf, P, DD_, DD_, DD_, DD_, Wo_b, nullptr, 0);

    // --- h = LN(x + P) fp32;  f = LN(h) tf32-rounded
    ln_row<false><<<NN_, TH>>>(x, P, ln1_g, ln1_b, Hb);
    ln_row<true><<<NN_, TH>>>(Hb, nullptr, ffn_ln_g, ffn_ln_b, Fb);

    // --- FFN1 with fused exact GELU (output tf32-rounded for FFN2)
    dim3 gf1(FF_ / BN, NN_ / BM);
    gemm_tc<2, true><<<gf1, TH, GEMM_SMEM>>>(Fb, W1_tf, T, DD_, DD_, FF_, FF_, ffn_b1, nullptr, 0);

    // --- FFN2 + bias + residual h (fp32 out)
    dim3 gf2(DD_ / BN, NN_ / BM);
    gemm_tc<3, false><<<gf2, TH, GEMM_SMEM>>>(T, W2_tf, out, FF_, FF_, DD_, DD_, ffn_b2, Hb, DD_);
}

// round 15
// speedup vs baseline: 3.3063x; 1.0010x over previous
#include <cuda_runtime.h>
#include <math.h>

// Problem constants
#define NN_ 4096
#define DD_ 1024
#define HH_ 8
#define DH_ 128
#define FF_ 2048   // 2*D
#define D3_ 3072   // 3*D (fused QKV width)

static const size_t SZ_ND = (size_t)NN_ * DD_;      // 4,194,304

// Scratch layout (floats):
//  QKV    : 3*SZ_ND   (4096 x 3072, Q|K|V concatenated)
//  AO,P,Hb,Fb : 4*SZ_ND
//  T      : 2*SZ_ND
//  x_tf   : 1*SZ_ND
//  W3_tf  : 1024x3072 = 3M
//  Wo_tf  : 1M ; W1_tf : 2M ; W2_tf : 2M
__device__ float g_scratch[12 * 4194304ull];

// ---------------------------------------------------------------------------
// TF32 + cp.async helpers
// ---------------------------------------------------------------------------
__device__ __forceinline__ unsigned f2tf(float f) {
    unsigned u;
    asm("cvt.rna.tf32.f32 %0, %1;" : "=r"(u) : "f"(f));
    return u;
}

__device__ __forceinline__ void mma_tf32(float* d, const unsigned* a, const unsigned* b) {
    asm volatile(
        "mma.sync.aligned.m16n8k8.row.col.f32.tf32.tf32.f32 "
        "{%0,%1,%2,%3}, {%4,%5,%6,%7}, {%8,%9}, {%0,%1,%2,%3};"
        : "+f"(d[0]), "+f"(d[1]), "+f"(d[2]), "+f"(d[3])
        : "r"(a[0]), "r"(a[1]), "r"(a[2]), "r"(a[3]), "r"(b[0]), "r"(b[1]));
}

__device__ __forceinline__ unsigned sm_u32(const void* p) {
    return (unsigned)__cvta_generic_to_shared(p);
}
#define CPA16(s, g) asm volatile("cp.async.cg.shared.global [%0], [%1], 16;" :: "r"(s), "l"(g))
#define CPCOMMIT()  asm volatile("cp.async.commit_group;")
#define CPWAIT(n)   asm volatile("cp.async.wait_group %0;" :: "n"(n))

// ---------------------------------------------------------------------------
// Round to tf32: contiguous, and strided-concat (for packing Wq|Wk|Wv).
// ---------------------------------------------------------------------------
__global__ void __launch_bounds__(256) round_tf_k(
    const float* __restrict__ in, float* __restrict__ out, int n4)
{
    int i = blockIdx.x * 256 + threadIdx.x;
    if (i < n4) {
        float4 v = ((const float4*)in)[i];
        v.x = __uint_as_float(f2tf(v.x));
        v.y = __uint_as_float(f2tf(v.y));
        v.z = __uint_as_float(f2tf(v.z));
        v.w = __uint_as_float(f2tf(v.w));
        ((float4*)out)[i] = v;
    }
}

__global__ void __launch_bounds__(256) round_tf_cat_k(
    const float* __restrict__ in, float* __restrict__ out,
    int cols4, int out_ld4, int col_off4, int n4)
{
    int i = blockIdx.x * 256 + threadIdx.x;
    if (i < n4) {
        int row = i / cols4;
        int c4  = i - row * cols4;
        float4 v = ((const float4*)in)[i];
        v.x = __uint_as_float(f2tf(v.x));
        v.y = __uint_as_float(f2tf(v.y));
        v.z = __uint_as_float(f2tf(v.z));
        v.w = __uint_as_float(f2tf(v.w));
        ((float4*)out)[(size_t)row * out_ld4 + col_off4 + c4] = v;
    }
}

// ---------------------------------------------------------------------------
// TF32 tensor-core GEMM: C = A @ B.  128x128 tile, BK=32, 2-stage cp.async.
// Operands pre-rounded to tf32. EPI: 0 none, 1 +bias, 2 gelu(+bias), 3 +bias+addm
// ---------------------------------------------------------------------------
#define BM 128
#define BN 128
#define GBK 32
#define A_LD 36
#define B_LD 136
#define A_SZ (BM * A_LD)
#define B_SZ (GBK * B_LD)

template <int EPI, bool TFOUT>
__global__ void __launch_bounds__(256, 2) gemm_tc(
    const float* __restrict__ A, const float* __restrict__ B, float* __restrict__ C,
    int K, int lda, int ldb, int ldc,
    const float* __restrict__ bias,
    const float* __restrict__ addm, int ldadd)
{
    extern __shared__ float smg[];
    float* As = smg;               // 2 stages x 128x36
    float* Bs = smg + 2 * A_SZ;    // 2 stages x 32x136

    const int tid  = threadIdx.x;
    const int lane = tid & 31;
    const int wid  = tid >> 5;
    const int gid  = lane >> 2;
    const int tq   = lane & 3;
    const int wm0  = (wid & 3) * 32;
    const int wn0  = (wid >> 2) * 64;
    const int row0 = blockIdx.y * BM;
    const int col0 = blockIdx.x * BN;

    auto issue = [&](int st, int k0) {
        float* ad = As + st * A_SZ;
        float* bd = Bs + st * B_SZ;
#pragma unroll
        for (int i = 0; i < 4; i++) {
            int c = tid + i * 256;
            int row = c >> 3, ko = (c & 7) * 4;
            CPA16(sm_u32(ad + row * A_LD + ko), A + (size_t)(row0 + row) * lda + k0 + ko);
        }
#pragma unroll
        for (int i = 0; i < 4; i++) {
            int c = tid + i * 256;
            int row = c >> 5, no = (c & 31) * 4;
            CPA16(sm_u32(bd + row * B_LD + no), B + (size_t)(k0 + row) * ldb + col0 + no);
        }
        CPCOMMIT();
    };

    float acc[2][8][4];
#pragma unroll
    for (int mt = 0; mt < 2; mt++)
#pragma unroll
        for (int nt = 0; nt < 8; nt++)
#pragma unroll
            for (int c = 0; c < 4; c++) acc[mt][nt][c] = 0.f;

    const int KT = K / GBK;
    issue(0, 0);

    for (int it = 0; it < KT; it++) {
        if (it + 1 < KT) { issue((it + 1) & 1, (it + 1) * GBK); CPWAIT(1); }
        else             { CPWAIT(0); }
        __syncthreads();

        const float* Ab = As + (it & 1) * A_SZ;
        const float* Bb = Bs + (it & 1) * B_SZ;
#pragma unroll
        for (int ks = 0; ks < 4; ks++) {
            const int k8 = ks * 8;
            unsigned af[2][4], bf[8][2];
#pragma unroll
            for (int mt = 0; mt < 2; mt++) {
                const int m = wm0 + mt * 16 + gid;
                af[mt][0] = __float_as_uint(Ab[(m) * A_LD + k8 + tq]);
                af[mt][1] = __float_as_uint(Ab[(m + 8) * A_LD + k8 + tq]);
                af[mt][2] = __float_as_uint(Ab[(m) * A_LD + k8 + tq + 4]);
                af[mt][3] = __float_as_uint(Ab[(m + 8) * A_LD + k8 + tq + 4]);
            }
#pragma unroll
            for (int nt = 0; nt < 8; nt++) {
                const int n = wn0 + nt * 8 + gid;
                bf[nt][0] = __float_as_uint(Bb[(k8 + tq) * B_LD + n]);
                bf[nt][1] = __float_as_uint(Bb[(k8 + tq + 4) * B_LD + n]);
            }
#pragma unroll
            for (int mt = 0; mt < 2; mt++)
#pragma unroll
                for (int nt = 0; nt < 8; nt++)
                    mma_tf32(acc[mt][nt], af[mt], bf[nt]);
        }
        __syncthreads();
    }

    // -------- epilogue --------
#pragma unroll
    for (int mt = 0; mt < 2; mt++) {
        const int r = row0 + wm0 + mt * 16 + gid;
#pragma unroll
        for (int nt = 0; nt < 8; nt++) {
            const int c = col0 + wn0 + nt * 8 + 2 * tq;
            float v0 = acc[mt][nt][0];
            float v1 = acc[mt][nt][1];
            float v2 = acc[mt][nt][2];
            float v3 = acc[mt][nt][3];
            if (EPI == 1) {
                v0 += bias[c]; v1 += bias[c + 1];
                v2 += bias[c]; v3 += bias[c + 1];
            } else if (EPI == 2) {
                v0 += bias[c]; v1 += bias[c + 1];
                v2 += bias[c]; v3 += bias[c + 1];
                v0 = 0.5f * v0 * (1.f + erff(v0 * 0.70710678118654752f));
                v1 = 0.5f * v1 * (1.f + erff(v1 * 0.70710678118654752f));
                v2 = 0.5f * v2 * (1.f + erff(v2 * 0.70710678118654752f));
                v3 = 0.5f * v3 * (1.f + erff(v3 * 0.70710678118654752f));
            } else if (EPI == 3) {
                float2 m0 = *(const float2*)&addm[(size_t)r * ldadd + c];
                float2 m1 = *(const float2*)&addm[(size_t)(r + 8) * ldadd + c];
                v0 += bias[c] + m0.x;     v1 += bias[c + 1] + m0.y;
                v2 += bias[c] + m1.x;     v3 += bias[c + 1] + m1.y;
            }
            if (TFOUT) {
                v0 = __uint_as_float(f2tf(v0));
                v1 = __uint_as_float(f2tf(v1));
                v2 = __uint_as_float(f2tf(v2));
                v3 = __uint_as_float(f2tf(v3));
            }
            *(float2*)&C[(size_t)r * ldc + c] = make_float2(v0, v1);
            *(float2*)&C[(size_t)(r + 8) * ldc + c] = make_float2(v2, v3);
        }
    }
}

// ---------------------------------------------------------------------------
// Flash attention v5: 2 CTAs/SM. 128 threads (4 warps), QROWS=64, KTILE=32.
// Q/K/V pre-rounded tf32 with row stride ldk (=3072, fused QKV buffer).
// Q in smem (once), K/V 2-stage cp.async, P fragments via shuffles,
// adj loads hoisted above QK MMAs. smem = 100 KB -> 2 CTAs/SM.
// ---------------------------------------------------------------------------
#define QROWS 64
#define KTILE 32
#define FTH 128
#define Q_LDS 132
#define K_LDS 132
#define V_LDS 136
#define Q_SZ (QROWS * Q_LDS)
#define K_SZ (KTILE * K_LDS)
#define V_SZ (KTILE * V_LDS)

__global__ void __launch_bounds__(FTH, 2) flash_attn(
    const float* __restrict__ Qm, const float* __restrict__ Km,
    const float* __restrict__ Vm, int ldk,
    const float* __restrict__ adj,
    const float* __restrict__ adj_bias, float* __restrict__ AO, float scale)
{
    extern __shared__ float sm[];
    float* Qs  = sm;                       // 64 x 132  [row][dh]
    float* Kst = sm + Q_SZ;                // 2 x 32x132 [key][dh]
    float* Vst = Kst + 2 * K_SZ;           // 2 x 32x136 [key][dh]

    const int h  = blockIdx.x;
    const int q0 = blockIdx.y * QROWS;
    const int tid  = threadIdx.x;
    const int lane = tid & 31;
    const int wid  = tid >> 5;             // 0..3
    const int gid  = lane >> 2;
    const int tq   = lane & 3;
    const int wr0  = wid * 16;

    const float beta = adj_bias[h];

    // ---- Q tile: one cp.async group (64 rows x 128 floats) ----
    {
        const float* qb = Qm + (size_t)q0 * ldk + h * DH_;
#pragma unroll
        for (int i = 0; i < 16; i++) {
            int c = tid + i * FTH;
            int row = c >> 5, off = (c & 31) * 4;
            CPA16(sm_u32(Qs + row * Q_LDS + off), qb + (size_t)row * ldk + off);
        }
        CPCOMMIT();
    }

    auto issue = [&](int st, int j) {
        const float* kb = Km + (size_t)(j * KTILE) * ldk + h * DH_;
        const float* vb = Vm + (size_t)(j * KTILE) * ldk + h * DH_;
        float* kd = Kst + st * K_SZ;
        float* vd = Vst + st * V_SZ;
#pragma unroll
        for (int i = 0; i < 8; i++) {
            int c = tid + i * FTH;
            int row = c >> 5, off = (c & 31) * 4;
            CPA16(sm_u32(kd + row * K_LDS + off), kb + (size_t)row * ldk + off);
            CPA16(sm_u32(vd + row * V_LDS + off), vb + (size_t)row * ldk + off);
        }
        CPCOMMIT();
    };

    float o[16][4];
#pragma unroll
    for (int nt = 0; nt < 16; nt++)
#pragma unroll
        for (int c = 0; c < 4; c++) o[nt][c] = 0.f;
    float m0 = -1e30f, m1 = -1e30f, l0 = 0.f, l1 = 0.f;

    const int NT = NN_ / KTILE;
    issue(0, 0);

    const float* arow_base0 = adj + (size_t)(q0 + wr0 + gid) * NN_;
    const float* arow_base1 = arow_base0 + (size_t)8 * NN_;

    for (int j = 0; j < NT; j++) {
        if (j + 1 < NT) { issue((j + 1) & 1, j + 1); CPWAIT(1); }
        else            { CPWAIT(0); }
        __syncthreads();

        // ---- hoisted adj loads: in flight during the QK MMA block ----
        const int kj0 = j * KTILE;
        float2 aj0[4], aj1[4];
#pragma unroll
        for (int nt = 0; nt < 4; nt++) {
            const int c = kj0 + nt * 8 + 2 * tq;
            aj0[nt] = *(const float2*)(arow_base0 + c);
            aj1[nt] = *(const float2*)(arow_base1 + c);
        }

        const float* Kb = Kst + (j & 1) * K_SZ;
        const float* Vb = Vst + (j & 1) * V_SZ;
        const float* Qw0 = Qs + (wr0 + gid) * Q_LDS;
        const float* Qw8 = Qw0 + 8 * Q_LDS;

        // ---- S = Q K^T : 16 rows x 32 cols per warp ----
        float s[4][4];
#pragma unroll
        for (int nt = 0; nt < 4; nt++)
#pragma unroll
            for (int c = 0; c < 4; c++) s[nt][c] = 0.f;

#pragma unroll
        for (int ks = 0; ks < 16; ks++) {
            const int k8 = ks * 8;
            unsigned af[4];
            af[0] = __float_as_uint(Qw0[k8 + tq]);
            af[1] = __float_as_uint(Qw8[k8 + tq]);
            af[2] = __float_as_uint(Qw0[k8 + tq + 4]);
            af[3] = __float_as_uint(Qw8[k8 + tq + 4]);
#pragma unroll
            for (int nt = 0; nt < 4; nt++) {
                unsigned bf[2];
                bf[0] = __float_as_uint(Kb[(nt * 8 + gid) * K_LDS + k8 + tq]);
                bf[1] = __float_as_uint(Kb[(nt * 8 + gid) * K_LDS + k8 + tq + 4]);
                mma_tf32(s[nt], af, bf);
            }
        }

        // ---- scale + beta*adj ----
#pragma unroll
        for (int nt = 0; nt < 4; nt++) {
            s[nt][0] = s[nt][0] * scale + beta * aj0[nt].x;
            s[nt][1] = s[nt][1] * scale + beta * aj0[nt].y;
            s[nt][2] = s[nt][2] * scale + beta * aj1[nt].x;
            s[nt][3] = s[nt][3] * scale + beta * aj1[nt].y;
        }

        // ---- online softmax ----
        float mx0 = -1e30f, mx1 = -1e30f;
#pragma unroll
        for (int nt = 0; nt < 4; nt++) {
            mx0 = fmaxf(mx0, fmaxf(s[nt][0], s[nt][1]));
            mx1 = fmaxf(mx1, fmaxf(s[nt][2], s[nt][3]));
        }
        mx0 = fmaxf(mx0, __shfl_xor_sync(0xffffffffu, mx0, 1));
        mx0 = fmaxf(mx0, __shfl_xor_sync(0xffffffffu, mx0, 2));
        mx1 = fmaxf(mx1, __shfl_xor_sync(0xffffffffu, mx1, 1));
        mx1 = fmaxf(mx1, __shfl_xor_sync(0xffffffffu, mx1, 2));

        const float mn0 = fmaxf(m0, mx0);
        const float mn1 = fmaxf(m1, mx1);
        const float f0 = __expf(m0 - mn0);
        const float f1 = __expf(m1 - mn1);
        m0 = mn0; m1 = mn1;

        float sum0 = 0.f, sum1 = 0.f;
#pragma unroll
        for (int nt = 0; nt < 4; nt++) {
            s[nt][0] = __expf(s[nt][0] - mn0);
            s[nt][1] = __expf(s[nt][1] - mn0);
            s[nt][2] = __expf(s[nt][2] - mn1);
            s[nt][3] = __expf(s[nt][3] - mn1);
            sum0 += s[nt][0] + s[nt][1];
            sum1 += s[nt][2] + s[nt][3];
        }
        sum0 += __shfl_xor_sync(0xffffffffu, sum0, 1);
        sum0 += __shfl_xor_sync(0xffffffffu, sum0, 2);
        sum1 += __shfl_xor_sync(0xffffffffu, sum1, 1);
        sum1 += __shfl_xor_sync(0xffffffffu, sum1, 2);
        l0 = l0 * f0 + sum0;
        l1 = l1 * f1 + sum1;

#pragma unroll
        for (int nt = 0; nt < 16; nt++) {
            o[nt][0] *= f0; o[nt][1] *= f0;
            o[nt][2] *= f1; o[nt][3] *= f1;
        }

        // ---- O += P @ V : P A-fragments via shuffles ----
        const int src0 = (lane & 28) | (tq >> 1);
        const int src1 = src0 + 2;
        const bool odd = (tq & 1);
#pragma unroll
        for (int kt = 0; kt < 4; kt++) {
            float e0 = __shfl_sync(0xffffffffu, s[kt][0], src0);
            float e1 = __shfl_sync(0xffffffffu, s[kt][1], src0);
            float e2 = __shfl_sync(0xffffffffu, s[kt][2], src0);
            float e3 = __shfl_sync(0xffffffffu, s[kt][3], src0);
            float g0 = __shfl_sync(0xffffffffu, s[kt][0], src1);
            float g1 = __shfl_sync(0xffffffffu, s[kt][1], src1);
            float g2 = __shfl_sync(0xffffffffu, s[kt][2], src1);
            float g3 = __shfl_sync(0xffffffffu, s[kt][3], src1);
            unsigned af[4];
            af[0] = f2tf(odd ? e1 : e0);
            af[1] = f2tf(odd ? e3 : e2);
            af[2] = f2tf(odd ? g1 : g0);
            af[3] = f2tf(odd ? g3 : g2);
            const int k8 = kt * 8;
#pragma unroll
            for (int nt = 0; nt < 16; nt++) {
                unsigned bf[2];
                bf[0] = __float_as_uint(Vb[(k8 + tq) * V_LDS + nt * 8 + gid]);
                bf[1] = __float_as_uint(Vb[(k8 + tq + 4) * V_LDS + nt * 8 + gid]);
                mma_tf32(o[nt], af, bf);
            }
        }
        __syncthreads();
    }

    // ---- normalize, round to tf32 (consumed as GEMM A-operand), write ----
    const float inv0 = 1.0f / l0;
    const float inv1 = 1.0f / l1;
    float* o0 = AO + (size_t)(q0 + wr0 + gid) * DD_ + h * DH_;
    float* o1 = o0 + (size_t)8 * DD_;
#pragma unroll
    for (int nt = 0; nt < 16; nt++) {
        const int c = nt * 8 + 2 * tq;
        float a0 = __uint_as_float(f2tf(o[nt][0] * inv0));
        float a1 = __uint_as_float(f2tf(o[nt][1] * inv0));
        float a2 = __uint_as_float(f2tf(o[nt][2] * inv1));
        float a3 = __uint_as_float(f2tf(o[nt][3] * inv1));
        *(float2*)(o0 + c) = make_float2(a0, a1);
        *(float2*)(o1 + c) = make_float2(a2, a3);
    }
}

// ---------------------------------------------------------------------------
// Row LayerNorm over D=1024: out = LN(X + R) * g + b   (R optional)
// ---------------------------------------------------------------------------
template <bool TFOUT>
__global__ void __launch_bounds__(256) ln_row(
    const float* __restrict__ X, const float* __restrict__ R,
    const float* __restrict__ g, const float* __restrict__ b,
    float* __restrict__ out)
{
    __shared__ float red[256];
    const int tid = threadIdx.x;
    const size_t row = blockIdx.x;

    float4 v = ((const float4*)(X + row * DD_))[tid];
    if (R) {
        float4 r = ((const float4*)(R + row * DD_))[tid];
        v.x += r.x; v.y += r.y; v.z += r.z; v.w += r.w;
    }
    red[tid] = v.x + v.y + v.z + v.w;
    __syncthreads();
    for (int s = 128; s > 0; s >>= 1) {
        if (tid < s) red[tid] += red[tid + s];
        __syncthreads();
    }
    const float mu = red[0] * (1.0f / DD_);
    __syncthreads();

    float dx = v.x - mu, dy = v.y - mu, dz = v.z - mu, dw = v.w - mu;
    red[tid] = dx * dx + dy * dy + dz * dz + dw * dw;
    __syncthreads();
    for (int s = 128; s > 0; s >>= 1) {
        if (tid < s) red[tid] += red[tid + s];
        __syncthreads();
    }
    const float rs = rsqrtf(red[0] * (1.0f / DD_) + 1e-5f);

    float4 gg = ((const float4*)g)[tid];
    float4 bb = ((const float4*)b)[tid];
    float4 o;
    o.x = dx * rs * gg.x + bb.x;
    o.y = dy * rs * gg.y + bb.y;
    o.z = dz * rs * gg.z + bb.z;
    o.w = dw * rs * gg.w + bb.w;
    if (TFOUT) {
        o.x = __uint_as_float(f2tf(o.x));
        o.y = __uint_as_float(f2tf(o.y));
        o.z = __uint_as_float(f2tf(o.z));
        o.w = __uint_as_float(f2tf(o.w));
    }
    ((float4*)(out + row * DD_))[tid] = o;
}

// ---------------------------------------------------------------------------
extern "C" void kernel_launch(void* const* d_in, const int* in_sizes, int n_in,
                              void* d_out, int out_size)
{
    const float* x        = (const float*)d_in[0];
    const float* adj      = (const float*)d_in[1];
    const float* Wq       = (const float*)d_in[2];
    const float* Wk       = (const float*)d_in[3];
    const float* Wv       = (const float*)d_in[4];
    const float* Wo_w     = (const float*)d_in[5];
    const float* Wo_b     = (const float*)d_in[6];
    const float* adj_bias = (const float*)d_in[7];
    const float* ln1_g    = (const float*)d_in[8];
    const float* ln1_b    = (const float*)d_in[9];
    const float* ffn_ln_g = (const float*)d_in[10];
    const float* ffn_ln_b = (const float*)d_in[11];
    const float* ffn_w1   = (const float*)d_in[12];
    const float* ffn_b1   = (const float*)d_in[13];
    const float* ffn_w2   = (const float*)d_in[14];
    const float* ffn_b2   = (const float*)d_in[15];
    float* out = (float*)d_out;

    float* scr = nullptr;
    cudaGetSymbolAddress((void**)&scr, g_scratch);

    float* QKV  = scr;                          // 4096 x 3072
    float* AO   = scr + 3 * SZ_ND;
    float* P    = scr + 4 * SZ_ND;
    float* Hb   = scr + 5 * SZ_ND;
    float* Fb   = scr + 6 * SZ_ND;
    float* T    = scr + 7 * SZ_ND;              // 4096 x 2048
    float* x_tf = scr + 9 * SZ_ND;
    float* W3_tf = scr + 10 * SZ_ND;            // 1024 x 3072
    float* Wo_tf = W3_tf + (size_t)DD_ * D3_;   // 1M
    float* W1_tf = Wo_tf + (size_t)DD_ * DD_;   // 2M
    float* W2_tf = W1_tf + (size_t)DD_ * FF_;   // 2M

    const int TH = 256;
    const float scale = 0.08838834764831845f;  // 128^-0.5

    const int GEMM_SMEM  = (2 * A_SZ + 2 * B_SZ) * 4;                  // 71,680 B
    const int FLASH_SMEM = (Q_SZ + 2 * K_SZ + 2 * V_SZ) * 4;           // 102,400 B
    static int attr_set = 0;
    if (!attr_set) {
        cudaFuncSetAttribute(gemm_tc<0, true>,  cudaFuncAttributeMaxDynamicSharedMemorySize, GEMM_SMEM);
        cudaFuncSetAttribute(gemm_tc<1, false>, cudaFuncAttributeMaxDynamicSharedMemorySize, GEMM_SMEM);
        cudaFuncSetAttribute(gemm_tc<2, true>,  cudaFuncAttributeMaxDynamicSharedMemorySize, GEMM_SMEM);
        cudaFuncSetAttribute(gemm_tc<3, false>, cudaFuncAttributeMaxDynamicSharedMemorySize, GEMM_SMEM);
        cudaFuncSetAttribute(flash_attn, cudaFuncAttributeMaxDynamicSharedMemorySize, FLASH_SMEM);
        attr_set = 1;
    }

    const int W1M4 = DD_ * DD_ / 4;   // 1M floats / 4
    // --- Pre-round x; pack Wq|Wk|Wv into W3_tf; round other weights
    round_tf_k<<<(int)(SZ_ND / 4 + 255) / 256, TH>>>(x, x_tf, (int)(SZ_ND / 4));
    round_tf_cat_k<<<(W1M4 + 255) / 256, TH>>>(Wq, W3_tf, DD_ / 4, D3_ / 4, 0,            W1M4);
    round_tf_cat_k<<<(W1M4 + 255) / 256, TH>>>(Wk, W3_tf, DD_ / 4, D3_ / 4, DD_ / 4,      W1M4);
    round_tf_cat_k<<<(W1M4 + 255) / 256, TH>>>(Wv, W3_tf, DD_ / 4, D3_ / 4, 2 * DD_ / 4,  W1M4);
    round_tf_k<<<(W1M4 + 255) / 256, TH>>>(Wo_w, Wo_tf, W1M4);
    round_tf_k<<<(DD_ * FF_ / 4 + 255) / 256, TH>>>(ffn_w1, W1_tf, DD_ * FF_ / 4);
    round_tf_k<<<(FF_ * DD_ / 4 + 255) / 256, TH>>>(ffn_w2, W2_tf, FF_ * DD_ / 4);

    // --- Fused QKV projection: (4096x1024) @ (1024x3072), tf32-rounded out
    dim3 gqkv(D3_ / BN, NN_ / BM);
    gemm_tc<0, true><<<gqkv, TH, GEMM_SMEM>>>(x_tf, W3_tf, QKV, DD_, DD_, D3_, D3_,
                                              nullptr, nullptr, 0);

    // --- Fused attention; Q/K/V live in the packed QKV buffer (stride 3072)
    flash_attn<<<dim3(HH_, NN_ / QROWS), FTH, FLASH_SMEM>>>(
        QKV, QKV + DD_, QKV + 2 * DD_, D3_, adj, adj_bias, AO, scale);

    // --- Output projection with bias (fp32 out)
    dim3 gp(DD_ / BN, NN_ / BM);
    gemm_tc<1, false><<<gp, TH, GEMM_SMEM>>>(AO, Wo_tf, P, DD_, DD_, DD_, DD_, Wo_b, nullptr, 0);

    // --- h = LN(x + P) fp32;  f = LN(h) tf32-rounded
    ln_row<false><<<NN_, TH>>>(x, P, ln1_g, ln1_b, Hb);
    ln_row<true><<<NN_, TH>>>(Hb, nullptr, ffn_ln_g, ffn_ln_b, Fb);

    // --- FFN1 with fused exact GELU (output tf32-rounded for FFN2)
    dim3 gf1(FF_ / BN, NN_ / BM);
    gemm_tc<2, true><<<gf1, TH, GEMM_SMEM>>>(Fb, W1_tf, T, DD_, DD_, FF_, FF_, ffn_b1, nullptr, 0);

    // --- FFN2 + bias + residual h (fp32 out)
    dim3 gf2(DD_ / BN, NN_ / BM);
    gemm_tc<3, false><<<gf2, TH, GEMM_SMEM>>>(T, W2_tf, out, FF_, FF_, DD_, DD_, ffn_b2, Hb, DD_);
}

// round 16
// speedup vs baseline: 3.6459x; 1.1027x over previous
#include <cuda_runtime.h>
#include <math.h>

// Problem constants
#define NN_ 4096
#define DD_ 1024
#define HH_ 8
#define DH_ 128
#define FF_ 2048   // 2*D
#define D3_ 3072   // 3*D (fused QKV width)

static const size_t SZ_ND = (size_t)NN_ * DD_;      // 4,194,304

// Scratch layout (floats):
//  QKV : 3*SZ_ND | AO,P,Hb,Fb : 4*SZ_ND | T : 2*SZ_ND | x_tf : 1*SZ_ND
//  W3_tf : 3M | Wo_tf : 1M | W1_tf : 2M | W2_tf : 2M
__device__ float g_scratch[12 * 4194304ull];

// ---------------------------------------------------------------------------
// TF32 + cp.async helpers
// ---------------------------------------------------------------------------
__device__ __forceinline__ unsigned f2tf(float f) {
    unsigned u;
    asm("cvt.rna.tf32.f32 %0, %1;" : "=r"(u) : "f"(f));
    return u;
}

__device__ __forceinline__ void mma_tf32(float* d, const unsigned* a, const unsigned* b) {
    asm volatile(
        "mma.sync.aligned.m16n8k8.row.col.f32.tf32.tf32.f32 "
        "{%0,%1,%2,%3}, {%4,%5,%6,%7}, {%8,%9}, {%0,%1,%2,%3};"
        : "+f"(d[0]), "+f"(d[1]), "+f"(d[2]), "+f"(d[3])
        : "r"(a[0]), "r"(a[1]), "r"(a[2]), "r"(a[3]), "r"(b[0]), "r"(b[1]));
}

__device__ __forceinline__ unsigned sm_u32(const void* p) {
    return (unsigned)__cvta_generic_to_shared(p);
}
#define CPA16(s, g) asm volatile("cp.async.cg.shared.global [%0], [%1], 16;" :: "r"(s), "l"(g))
#define CPCOMMIT()  asm volatile("cp.async.commit_group;")
#define CPWAIT(n)   asm volatile("cp.async.wait_group %0;" :: "n"(n))

// ---------------------------------------------------------------------------
// Round to tf32: contiguous, and strided-concat (for packing Wq|Wk|Wv).
// ---------------------------------------------------------------------------
__global__ void __launch_bounds__(256) round_tf_k(
    const float* __restrict__ in, float* __restrict__ out, int n4)
{
    int i = blockIdx.x * 256 + threadIdx.x;
    if (i < n4) {
        float4 v = ((const float4*)in)[i];
        v.x = __uint_as_float(f2tf(v.x));
        v.y = __uint_as_float(f2tf(v.y));
        v.z = __uint_as_float(f2tf(v.z));
        v.w = __uint_as_float(f2tf(v.w));
        ((float4*)out)[i] = v;
    }
}

__global__ void __launch_bounds__(256) round_tf_cat_k(
    const float* __restrict__ in, float* __restrict__ out,
    int cols4, int out_ld4, int col_off4, int n4)
{
    int i = blockIdx.x * 256 + threadIdx.x;
    if (i < n4) {
        int row = i / cols4;
        int c4  = i - row * cols4;
        float4 v = ((const float4*)in)[i];
        v.x = __uint_as_float(f2tf(v.x));
        v.y = __uint_as_float(f2tf(v.y));
        v.z = __uint_as_float(f2tf(v.z));
        v.w = __uint_as_float(f2tf(v.w));
        ((float4*)out)[(size_t)row * out_ld4 + col_off4 + c4] = v;
    }
}

// ---------------------------------------------------------------------------
// TF32 GEMM v3: 128x128 CTA tile, 4 warps, 64x64 warp tile (LDS/MMA = 1.0).
// BK=32, 2-stage cp.async, operands pre-rounded tf32.
// EPI: 0 none, 1 +bias, 2 gelu(+bias), 3 +bias+addm
// ---------------------------------------------------------------------------
#define BM 128
#define BN 128
#define GBK 32
#define GTH 128
#define A_LD 36
#define B_LD 136
#define A_SZ (BM * A_LD)
#define B_SZ (GBK * B_LD)

template <int EPI, bool TFOUT>
__global__ void __launch_bounds__(GTH, 2) gemm_tc(
    const float* __restrict__ A, const float* __restrict__ B, float* __restrict__ C,
    int K, int lda, int ldb, int ldc,
    const float* __restrict__ bias,
    const float* __restrict__ addm, int ldadd)
{
    extern __shared__ float smg[];
    float* As = smg;               // 2 stages x 128x36
    float* Bs = smg + 2 * A_SZ;    // 2 stages x 32x136

    const int tid  = threadIdx.x;
    const int lane = tid & 31;
    const int wid  = tid >> 5;          // 0..3
    const int gid  = lane >> 2;
    const int tq   = lane & 3;
    const int wm0  = (wid & 1) * 64;
    const int wn0  = (wid >> 1) * 64;
    const int row0 = blockIdx.y * BM;
    const int col0 = blockIdx.x * BN;

    auto issue = [&](int st, int k0) {
        float* ad = As + st * A_SZ;
        float* bd = Bs + st * B_SZ;
#pragma unroll
        for (int i = 0; i < 8; i++) {
            int c = tid + i * GTH;
            int row = c >> 3, ko = (c & 7) * 4;
            CPA16(sm_u32(ad + row * A_LD + ko), A + (size_t)(row0 + row) * lda + k0 + ko);
        }
#pragma unroll
        for (int i = 0; i < 8; i++) {
            int c = tid + i * GTH;
            int row = c >> 5, no = (c & 31) * 4;
            CPA16(sm_u32(bd + row * B_LD + no), B + (size_t)(k0 + row) * ldb + col0 + no);
        }
        CPCOMMIT();
    };

    float acc[4][8][4];
#pragma unroll
    for (int mt = 0; mt < 4; mt++)
#pragma unroll
        for (int nt = 0; nt < 8; nt++)
#pragma unroll
            for (int c = 0; c < 4; c++) acc[mt][nt][c] = 0.f;

    const int KT = K / GBK;
    issue(0, 0);

    for (int it = 0; it < KT; it++) {
        if (it + 1 < KT) { issue((it + 1) & 1, (it + 1) * GBK); CPWAIT(1); }
        else             { CPWAIT(0); }
        __syncthreads();

        const float* Ab = As + (it & 1) * A_SZ;
        const float* Bb = Bs + (it & 1) * B_SZ;
#pragma unroll
        for (int ks = 0; ks < 4; ks++) {
            const int k8 = ks * 8;
            unsigned af[4][4], bf[8][2];
#pragma unroll
            for (int mt = 0; mt < 4; mt++) {
                const int m = wm0 + mt * 16 + gid;
                af[mt][0] = __float_as_uint(Ab[(m) * A_LD + k8 + tq]);
                af[mt][1] = __float_as_uint(Ab[(m + 8) * A_LD + k8 + tq]);
                af[mt][2] = __float_as_uint(Ab[(m) * A_LD + k8 + tq + 4]);
                af[mt][3] = __float_as_uint(Ab[(m + 8) * A_LD + k8 + tq + 4]);
            }
#pragma unroll
            for (int nt = 0; nt < 8; nt++) {
                const int n = wn0 + nt * 8 + gid;
                bf[nt][0] = __float_as_uint(Bb[(k8 + tq) * B_LD + n]);
                bf[nt][1] = __float_as_uint(Bb[(k8 + tq + 4) * B_LD + n]);
            }
#pragma unroll
            for (int mt = 0; mt < 4; mt++)
#pragma unroll
                for (int nt = 0; nt < 8; nt++)
                    mma_tf32(acc[mt][nt], af[mt], bf[nt]);
        }
        __syncthreads();
    }

    // -------- epilogue --------
#pragma unroll
    for (int mt = 0; mt < 4; mt++) {
        const int r = row0 + wm0 + mt * 16 + gid;
#pragma unroll
        for (int nt = 0; nt < 8; nt++) {
            const int c = col0 + wn0 + nt * 8 + 2 * tq;
            float v0 = acc[mt][nt][0];
            float v1 = acc[mt][nt][1];
            float v2 = acc[mt][nt][2];
            float v3 = acc[mt][nt][3];
            if (EPI == 1) {
                v0 += bias[c]; v1 += bias[c + 1];
                v2 += bias[c]; v3 += bias[c + 1];
            } else if (EPI == 2) {
                v0 += bias[c]; v1 += bias[c + 1];
                v2 += bias[c]; v3 += bias[c + 1];
                v0 = 0.5f * v0 * (1.f + erff(v0 * 0.70710678118654752f));
                v1 = 0.5f * v1 * (1.f + erff(v1 * 0.70710678118654752f));
                v2 = 0.5f * v2 * (1.f + erff(v2 * 0.70710678118654752f));
                v3 = 0.5f * v3 * (1.f + erff(v3 * 0.70710678118654752f));
            } else if (EPI == 3) {
                float2 m0 = *(const float2*)&addm[(size_t)r * ldadd + c];
                float2 m1 = *(const float2*)&addm[(size_t)(r + 8) * ldadd + c];
                v0 += bias[c] + m0.x;     v1 += bias[c + 1] + m0.y;
                v2 += bias[c] + m1.x;     v3 += bias[c + 1] + m1.y;
            }
            if (TFOUT) {
                v0 = __uint_as_float(f2tf(v0));
                v1 = __uint_as_float(f2tf(v1));
                v2 = __uint_as_float(f2tf(v2));
                v3 = __uint_as_float(f2tf(v3));
            }
            *(float2*)&C[(size_t)r * ldc + c] = make_float2(v0, v1);
            *(float2*)&C[(size_t)(r + 8) * ldc + c] = make_float2(v2, v3);
        }
    }
}

// ---------------------------------------------------------------------------
// Flash attention v6: QROWS=256, 8 warps, each warp 32 q-rows (2 row-tiles);
// K/V fragments reused across both row-tiles (LDS/MMA 2.5 -> 1.5).
// KTILE=32, 2-stage cp.async, Q/K/V pre-rounded tf32 (stride ldk=3072).
// smem: Qs 256x132 | K 2x32x132 | V 2x32x136 = 203,776 B (1 CTA/SM).
// ---------------------------------------------------------------------------
#define QROWS 256
#define KTILE 32
#define FTH 256
#define Q_LDS 132
#define K_LDS 132
#define V_LDS 136
#define Q_SZ (QROWS * Q_LDS)
#define K_SZ (KTILE * K_LDS)
#define V_SZ (KTILE * V_LDS)

__global__ void __launch_bounds__(FTH, 1) flash_attn(
    const float* __restrict__ Qm, const float* __restrict__ Km,
    const float* __restrict__ Vm, int ldk,
    const float* __restrict__ adj,
    const float* __restrict__ adj_bias, float* __restrict__ AO, float scale)
{
    extern __shared__ float sm[];
    float* Qs  = sm;                       // 256 x 132 [row][dh]
    float* Kst = sm + Q_SZ;                // 2 x 32x132 [key][dh]
    float* Vst = Kst + 2 * K_SZ;           // 2 x 32x136 [key][dh]

    const int h  = blockIdx.x;
    const int q0 = blockIdx.y * QROWS;
    const int tid  = threadIdx.x;
    const int lane = tid & 31;
    const int wid  = tid >> 5;             // 0..7
    const int gid  = lane >> 2;
    const int tq   = lane & 3;
    const int wr0  = wid * 32;             // warp's q-row base (32 rows/warp)

    const float beta = adj_bias[h];

    // ---- Q tile: 256 rows x 128 floats, one cp.async group ----
    {
        const float* qb = Qm + (size_t)q0 * ldk + h * DH_;
#pragma unroll
        for (int i = 0; i < 32; i++) {
            int c = tid + i * FTH;
            int row = c >> 5, off = (c & 31) * 4;
            CPA16(sm_u32(Qs + row * Q_LDS + off), qb + (size_t)row * ldk + off);
        }
        CPCOMMIT();
    }

    auto issue = [&](int st, int j) {
        const float* kb = Km + (size_t)(j * KTILE) * ldk + h * DH_;
        const float* vb = Vm + (size_t)(j * KTILE) * ldk + h * DH_;
        float* kd = Kst + st * K_SZ;
        float* vd = Vst + st * V_SZ;
#pragma unroll
        for (int i = 0; i < 4; i++) {
            int c = tid + i * FTH;
            int row = c >> 5, off = (c & 31) * 4;
            CPA16(sm_u32(kd + row * K_LDS + off), kb + (size_t)row * ldk + off);
            CPA16(sm_u32(vd + row * V_LDS + off), vb + (size_t)row * ldk + off);
        }
        CPCOMMIT();
    };

    // o[rt][nt][4] : rows wr0+rt*16+{gid,gid+8}, dh cols nt*8+2tq(+1)
    float o[2][16][4];
#pragma unroll
    for (int rt = 0; rt < 2; rt++)
#pragma unroll
        for (int nt = 0; nt < 16; nt++)
#pragma unroll
            for (int c = 0; c < 4; c++) o[rt][nt][c] = 0.f;
    // softmax state per row-group g (g = rt*2 + half): rows wr0 + g*8 + gid
    float mR[4] = {-1e30f, -1e30f, -1e30f, -1e30f};
    float lR[4] = {0.f, 0.f, 0.f, 0.f};

    const int NT = NN_ / KTILE;
    issue(0, 0);

    const float* arow[4];
#pragma unroll
    for (int g = 0; g < 4; g++)
        arow[g] = adj + (size_t)(q0 + wr0 + g * 8 + gid) * NN_;

    for (int j = 0; j < NT; j++) {
        if (j + 1 < NT) { issue((j + 1) & 1, j + 1); CPWAIT(1); }
        else            { CPWAIT(0); }
        __syncthreads();

        // ---- hoisted adj loads (in flight during QK MMA block) ----
        const int kj0 = j * KTILE;
        float2 aj[4][4];
#pragma unroll
        for (int g = 0; g < 4; g++)
#pragma unroll
            for (int nt = 0; nt < 4; nt++)
                aj[g][nt] = *(const float2*)(arow[g] + kj0 + nt * 8 + 2 * tq);

        const float* Kb = Kst + (j & 1) * K_SZ;
        const float* Vb = Vst + (j & 1) * V_SZ;

        // ---- S = Q K^T : 32 rows x 32 keys per warp, K-frags reused x2 ----
        float s[2][4][4];
#pragma unroll
        for (int rt = 0; rt < 2; rt++)
#pragma unroll
            for (int nt = 0; nt < 4; nt++)
#pragma unroll
                for (int c = 0; c < 4; c++) s[rt][nt][c] = 0.f;

#pragma unroll
        for (int ks = 0; ks < 16; ks++) {
            const int k8 = ks * 8;
            unsigned af[2][4];
#pragma unroll
            for (int rt = 0; rt < 2; rt++) {
                const float* Qw = Qs + (wr0 + rt * 16 + gid) * Q_LDS + k8;
                const float* Qw8 = Qw + 8 * Q_LDS;
                af[rt][0] = __float_as_uint(Qw[tq]);
                af[rt][1] = __float_as_uint(Qw8[tq]);
                af[rt][2] = __float_as_uint(Qw[tq + 4]);
                af[rt][3] = __float_as_uint(Qw8[tq + 4]);
            }
#pragma unroll
            for (int nt = 0; nt < 4; nt++) {
                unsigned bf[2];
                bf[0] = __float_as_uint(Kb[(nt * 8 + gid) * K_LDS + k8 + tq]);
                bf[1] = __float_as_uint(Kb[(nt * 8 + gid) * K_LDS + k8 + tq + 4]);
                mma_tf32(s[0][nt], af[0], bf);
                mma_tf32(s[1][nt], af[1], bf);
            }
        }

        // ---- scale + beta*adj ----
#pragma unroll
        for (int rt = 0; rt < 2; rt++)
#pragma unroll
            for (int nt = 0; nt < 4; nt++) {
                s[rt][nt][0] = s[rt][nt][0] * scale + beta * aj[2 * rt][nt].x;
                s[rt][nt][1] = s[rt][nt][1] * scale + beta * aj[2 * rt][nt].y;
                s[rt][nt][2] = s[rt][nt][2] * scale + beta * aj[2 * rt + 1][nt].x;
                s[rt][nt][3] = s[rt][nt][3] * scale + beta * aj[2 * rt + 1][nt].y;
            }

        // ---- online softmax (per row-group) ----
        float fg[4];
#pragma unroll
        for (int rt = 0; rt < 2; rt++) {
            float mx0 = -1e30f, mx1 = -1e30f;
#pragma unroll
            for (int nt = 0; nt < 4; nt++) {
                mx0 = fmaxf(mx0, fmaxf(s[rt][nt][0], s[rt][nt][1]));
                mx1 = fmaxf(mx1, fmaxf(s[rt][nt][2], s[rt][nt][3]));
            }
            mx0 = fmaxf(mx0, __shfl_xor_sync(0xffffffffu, mx0, 1));
            mx0 = fmaxf(mx0, __shfl_xor_sync(0xffffffffu, mx0, 2));
            mx1 = fmaxf(mx1, __shfl_xor_sync(0xffffffffu, mx1, 1));
            mx1 = fmaxf(mx1, __shfl_xor_sync(0xffffffffu, mx1, 2));

            const float mn0 = fmaxf(mR[2 * rt], mx0);
            const float mn1 = fmaxf(mR[2 * rt + 1], mx1);
            fg[2 * rt]     = __expf(mR[2 * rt] - mn0);
            fg[2 * rt + 1] = __expf(mR[2 * rt + 1] - mn1);
            mR[2 * rt] = mn0; mR[2 * rt + 1] = mn1;

            float sum0 = 0.f, sum1 = 0.f;
#pragma unroll
            for (int nt = 0; nt < 4; nt++) {
                s[rt][nt][0] = __expf(s[rt][nt][0] - mn0);
                s[rt][nt][1] = __expf(s[rt][nt][1] - mn0);
                s[rt][nt][2] = __expf(s[rt][nt][2] - mn1);
                s[rt][nt][3] = __expf(s[rt][nt][3] - mn1);
                sum0 += s[rt][nt][0] + s[rt][nt][1];
                sum1 += s[rt][nt][2] + s[rt][nt][3];
            }
            sum0 += __shfl_xor_sync(0xffffffffu, sum0, 1);
            sum0 += __shfl_xor_sync(0xffffffffu, sum0, 2);
            sum1 += __shfl_xor_sync(0xffffffffu, sum1, 1);
            sum1 += __shfl_xor_sync(0xffffffffu, sum1, 2);
            lR[2 * rt]     = lR[2 * rt] * fg[2 * rt] + sum0;
            lR[2 * rt + 1] = lR[2 * rt + 1] * fg[2 * rt + 1] + sum1;
        }

#pragma unroll
        for (int rt = 0; rt < 2; rt++)
#pragma unroll
            for (int nt = 0; nt < 16; nt++) {
                o[rt][nt][0] *= fg[2 * rt];     o[rt][nt][1] *= fg[2 * rt];
                o[rt][nt][2] *= fg[2 * rt + 1]; o[rt][nt][3] *= fg[2 * rt + 1];
            }

        // ---- O += P @ V : P-frags via shuffles, V-frags reused x2 ----
        const int src0 = (lane & 28) | (tq >> 1);
        const int src1 = src0 + 2;
        const bool odd = (tq & 1);
#pragma unroll
        for (int kt = 0; kt < 4; kt++) {
            unsigned pf[2][4];
#pragma unroll
            for (int rt = 0; rt < 2; rt++) {
                float e0 = __shfl_sync(0xffffffffu, s[rt][kt][0], src0);
                float e1 = __shfl_sync(0xffffffffu, s[rt][kt][1], src0);
                float e2 = __shfl_sync(0xffffffffu, s[rt][kt][2], src0);
                float e3 = __shfl_sync(0xffffffffu, s[rt][kt][3], src0);
                float g0 = __shfl_sync(0xffffffffu, s[rt][kt][0], src1);
                float g1 = __shfl_sync(0xffffffffu, s[rt][kt][1], src1);
                float g2 = __shfl_sync(0xffffffffu, s[rt][kt][2], src1);
                float g3 = __shfl_sync(0xffffffffu, s[rt][kt][3], src1);
                pf[rt][0] = f2tf(odd ? e1 : e0);
                pf[rt][1] = f2tf(odd ? e3 : e2);
                pf[rt][2] = f2tf(odd ? g1 : g0);
                pf[rt][3] = f2tf(odd ? g3 : g2);
            }
            const int k8 = kt * 8;
#pragma unroll
            for (int nt = 0; nt < 16; nt++) {
                unsigned bf[2];
                bf[0] = __float_as_uint(Vb[(k8 + tq) * V_LDS + nt * 8 + gid]);
                bf[1] = __float_as_uint(Vb[(k8 + tq + 4) * V_LDS + nt * 8 + gid]);
                mma_tf32(o[0][nt], pf[0], bf);
                mma_tf32(o[1][nt], pf[1], bf);
            }
        }
        __syncthreads();
    }

    // ---- normalize, round to tf32 (consumed as GEMM A-operand), write ----
    float inv[4];
#pragma unroll
    for (int g = 0; g < 4; g++) inv[g] = 1.0f / lR[g];

#pragma unroll
    for (int rt = 0; rt < 2; rt++) {
        float* o0 = AO + (size_t)(q0 + wr0 + rt * 16 + gid) * DD_ + h * DH_;
        float* o1 = o0 + (size_t)8 * DD_;
#pragma unroll
        for (int nt = 0; nt < 16; nt++) {
            const int c = nt * 8 + 2 * tq;
            float a0 = __uint_as_float(f2tf(o[rt][nt][0] * inv[2 * rt]));
            float a1 = __uint_as_float(f2tf(o[rt][nt][1] * inv[2 * rt]));
            float a2 = __uint_as_float(f2tf(o[rt][nt][2] * inv[2 * rt + 1]));
            float a3 = __uint_as_float(f2tf(o[rt][nt][3] * inv[2 * rt + 1]));
            *(float2*)(o0 + c) = make_float2(a0, a1);
            *(float2*)(o1 + c) = make_float2(a2, a3);
        }
    }
}

// ---------------------------------------------------------------------------
// Row LayerNorm over D=1024: out = LN(X + R) * g + b   (R optional)
// ---------------------------------------------------------------------------
template <bool TFOUT>
__global__ void __launch_bounds__(256) ln_row(
    const float* __restrict__ X, const float* __restrict__ R,
    const float* __restrict__ g, const float* __restrict__ b,
    float* __restrict__ out)
{
    __shared__ float red[256];
    const int tid = threadIdx.x;
    const size_t row = blockIdx.x;

    float4 v = ((const float4*)(X + row * DD_))[tid];
    if (R) {
        float4 r = ((const float4*)(R + row * DD_))[tid];
        v.x += r.x; v.y += r.y; v.z += r.z; v.w += r.w;
    }
    red[tid] = v.x + v.y + v.z + v.w;
    __syncthreads();
    for (int s = 128; s > 0; s >>= 1) {
        if (tid < s) red[tid] += red[tid + s];
        __syncthreads();
    }
    const float mu = red[0] * (1.0f / DD_);
    __syncthreads();

    float dx = v.x - mu, dy = v.y - mu, dz = v.z - mu, dw = v.w - mu;
    red[tid] = dx * dx + dy * dy + dz * dz + dw * dw;
    __syncthreads();
    for (int s = 128; s > 0; s >>= 1) {
        if (tid < s) red[tid] += red[tid + s];
        __syncthreads();
    }
    const float rs = rsqrtf(red[0] * (1.0f / DD_) + 1e-5f);

    float4 gg = ((const float4*)g)[tid];
    float4 bb = ((const float4*)b)[tid];
    float4 o;
    o.x = dx * rs * gg.x + bb.x;
    o.y = dy * rs * gg.y + bb.y;
    o.z = dz * rs * gg.z + bb.z;
    o.w = dw * rs * gg.w + bb.w;
    if (TFOUT) {
        o.x = __uint_as_float(f2tf(o.x));
        o.y = __uint_as_float(f2tf(o.y));
        o.z = __uint_as_float(f2tf(o.z));
        o.w = __uint_as_float(f2tf(o.w));
    }
    ((float4*)(out + row * DD_))[tid] = o;
}

// ---------------------------------------------------------------------------
extern "C" void kernel_launch(void* const* d_in, const int* in_sizes, int n_in,
                              void* d_out, int out_size)
{
    const float* x        = (const float*)d_in[0];
    const float* adj      = (const float*)d_in[1];
    const float* Wq       = (const float*)d_in[2];
    const float* Wk       = (const float*)d_in[3];
    const float* Wv       = (const float*)d_in[4];
    const float* Wo_w     = (const float*)d_in[5];
    const float* Wo_b     = (const float*)d_in[6];
    const float* adj_bias = (const float*)d_in[7];
    const float* ln1_g    = (const float*)d_in[8];
    const float* ln1_b    = (const float*)d_in[9];
    const float* ffn_ln_g = (const float*)d_in[10];
    const float* ffn_ln_b = (const float*)d_in[11];
    const float* ffn_w1   = (const float*)d_in[12];
    const float* ffn_b1   = (const float*)d_in[13];
    const float* ffn_w2   = (const float*)d_in[14];
    const float* ffn_b2   = (const float*)d_in[15];
    float* out = (float*)d_out;

    float* scr = nullptr;
    cudaGetSymbolAddress((void**)&scr, g_scratch);

    float* QKV  = scr;                          // 4096 x 3072
    float* AO   = scr + 3 * SZ_ND;
    float* P    = scr + 4 * SZ_ND;
    float* Hb   = scr + 5 * SZ_ND;
    float* Fb   = scr + 6 * SZ_ND;
    float* T    = scr + 7 * SZ_ND;              // 4096 x 2048
    float* x_tf = scr + 9 * SZ_ND;
    float* W3_tf = scr + 10 * SZ_ND;            // 1024 x 3072
    float* Wo_tf = W3_tf + (size_t)DD_ * D3_;
    float* W1_tf = Wo_tf + (size_t)DD_ * DD_;
    float* W2_tf = W1_tf + (size_t)DD_ * FF_;

    const float scale = 0.08838834764831845f;  // 128^-0.5

    const int GEMM_SMEM  = (2 * A_SZ + 2 * B_SZ) * 4;                  // 71,680 B
    const int FLASH_SMEM = (Q_SZ + 2 * K_SZ + 2 * V_SZ) * 4;           // 203,776 B
    static int attr_set = 0;
    if (!attr_set) {
        cudaFuncSetAttribute(gemm_tc<0, true>,  cudaFuncAttributeMaxDynamicSharedMemorySize, GEMM_SMEM);
        cudaFuncSetAttribute(gemm_tc<1, false>, cudaFuncAttributeMaxDynamicSharedMemorySize, GEMM_SMEM);
        cudaFuncSetAttribute(gemm_tc<2, true>,  cudaFuncAttributeMaxDynamicSharedMemorySize, GEMM_SMEM);
        cudaFuncSetAttribute(gemm_tc<3, false>, cudaFuncAttributeMaxDynamicSharedMemorySize, GEMM_SMEM);
        cudaFuncSetAttribute(flash_attn, cudaFuncAttributeMaxDynamicSharedMemorySize, FLASH_SMEM);
        attr_set = 1;
    }

    const int W1M4 = DD_ * DD_ / 4;
    // --- Pre-round x; pack Wq|Wk|Wv into W3_tf; round other weights
    round_tf_k<<<(int)(SZ_ND / 4 + 255) / 256, 256>>>(x, x_tf, (int)(SZ_ND / 4));
    round_tf_cat_k<<<(W1M4 + 255) / 256, 256>>>(Wq, W3_tf, DD_ / 4, D3_ / 4, 0,           W1M4);
    round_tf_cat_k<<<(W1M4 + 255) / 256, 256>>>(Wk, W3_tf, DD_ / 4, D3_ / 4, DD_ / 4,     W1M4);
    round_tf_cat_k<<<(W1M4 + 255) / 256, 256>>>(Wv, W3_tf, DD_ / 4, D3_ / 4, 2 * DD_ / 4, W1M4);
    round_tf_k<<<(W1M4 + 255) / 256, 256>>>(Wo_w, Wo_tf, W1M4);
    round_tf_k<<<(DD_ * FF_ / 4 + 255) / 256, 256>>>(ffn_w1, W1_tf, DD_ * FF_ / 4);
    round_tf_k<<<(FF_ * DD_ / 4 + 255) / 256, 256>>>(ffn_w2, W2_tf, FF_ * DD_ / 4);

    // --- Fused QKV projection: (4096x1024) @ (1024x3072), tf32-rounded out
    dim3 gqkv(D3_ / BN, NN_ / BM);
    gemm_tc<0, true><<<gqkv, GTH, GEMM_SMEM>>>(x_tf, W3_tf, QKV, DD_, DD_, D3_, D3_,
                                               nullptr, nullptr, 0);

    // --- Fused attention; Q/K/V in packed QKV buffer (row stride 3072)
    flash_attn<<<dim3(HH_, NN_ / QROWS), FTH, FLASH_SMEM>>>(
        QKV, QKV + DD_, QKV + 2 * DD_, D3_, adj, adj_bias, AO, scale);

    // --- Output projection with bias (fp32 out)
    dim3 gp(DD_ / BN, NN_ / BM);
    gemm_tc<1, false><<<gp, GTH, GEMM_SMEM>>>(AO, Wo_tf, P, DD_, DD_, DD_, DD_, Wo_b, nullptr, 0);

    // --- h = LN(x + P) fp32;  f = LN(h) tf32-rounded
    ln_row<false><<<NN_, 256>>>(x, P, ln1_g, ln1_b, Hb);
    ln_row<true><<<NN_, 256>>>(Hb, nullptr, ffn_ln_g, ffn_ln_b, Fb);

    // --- FFN1 with fused exact GELU (output tf32-rounded for FFN2)
    dim3 gf1(FF_ / BN, NN_ / BM);
    gemm_tc<2, true><<<gf1, GTH, GEMM_SMEM>>>(Fb, W1_tf, T, DD_, DD_, FF_, FF_, ffn_b1, nullptr, 0);

    // --- FFN2 + bias + residual h (fp32 out)
    dim3 gf2(DD_ / BN, NN_ / BM);
    gemm_tc<3, false><<<gf2, GTH, GEMM_SMEM>>>(T, W2_tf, out, FF_, FF_, DD_, DD_, ffn_b2, Hb, DD_);
}